// round 14
// baseline (speedup 1.0000x reference)
#include <cuda_runtime.h>
#include <cuda_fp16.h>
#include <math.h>
#include <stdint.h>

#define NPTS 16384
#define DIM  192
#define NS   16
#define NH   6
#define HD   32
#define KSP  16
#define DQ   48

// ---------------- scratch (device globals; no allocs allowed) ----------------
__device__ float g_xpw[NPTS * DIM];
__device__ float g_qkv[NPTS * 576];
__device__ float g_A[3L * NPTS * DIM];
__device__ float g_knnxyz[NPTS * 48];
__device__ float g_m3[NPTS * 3];
__device__ float g_distsum[NPTS];
__device__ float g_distmax[NPTS];
__device__ double g_ch[3 * DIM * 5];
__device__ double g_Sm3[3];
__device__ double g_SM33[6];
__device__ double g_sumdist;
__device__ int    g_maxbits;
__device__ float g_S[9 * DIM];
__device__ float g_bnscale[3 * DIM];
__device__ float g_bnshift[3 * DIM];
__device__ float g_volvec[DIM];
__device__ float g_kpwproj[DQ];
__device__ float g_kpconst;
__device__ __half g_Wh[184320];            // dense weights as half, [n][k=192]
__device__ uint32_t g_W1t[48 * 576];       // pos_W1 as tf32 bits
__device__ float g_bfq[576];               // fus_b @ W_qkv
__device__ uint32_t g_W2f[55296];          // pos_W2 fp16 mma fragments (m=2 slice used)
__device__ uint2 g_W2u[18432];             // W2^T fragments for U-mma, [m(2)][h][nt][ks][lane]
__device__ __half g_xh[NPTS * DIM];        // x as half
__device__ __half g_prefh[NPTS * DIM];     // prefus as half
__device__ __half g_atth[NPTS * DIM];      // attn out as half

#define OFF_PROP 0
#define OFF_QKV  36864
#define OFF_PROJ 147456

__device__ __forceinline__ void mma_f16(float* c, const uint32_t* a, uint32_t b0, uint32_t b1) {
    asm volatile("mma.sync.aligned.m16n8k16.row.col.f32.f16.f16.f32 "
        "{%0,%1,%2,%3}, {%4,%5,%6,%7}, {%8,%9}, {%0,%1,%2,%3};"
        : "+f"(c[0]), "+f"(c[1]), "+f"(c[2]), "+f"(c[3])
        : "r"(a[0]), "r"(a[1]), "r"(a[2]), "r"(a[3]), "r"(b0), "r"(b1));
}
__device__ __forceinline__ void mma_tf32(float* c, const uint32_t* a, uint32_t b0, uint32_t b1) {
    asm volatile("mma.sync.aligned.m16n8k8.row.col.f32.tf32.tf32.f32 "
        "{%0,%1,%2,%3}, {%4,%5,%6,%7}, {%8,%9}, {%0,%1,%2,%3};"
        : "+f"(c[0]), "+f"(c[1]), "+f"(c[2]), "+f"(c[3])
        : "r"(a[0]), "r"(a[1]), "r"(a[2]), "r"(a[3]), "r"(b0), "r"(b1));
}
__device__ __forceinline__ void ldm_x4(uint32_t* d, uint32_t a) {
    asm volatile("ldmatrix.sync.aligned.m8n8.x4.shared.b16 {%0,%1,%2,%3}, [%4];"
        : "=r"(d[0]), "=r"(d[1]), "=r"(d[2]), "=r"(d[3]) : "r"(a));
}
__device__ __forceinline__ uint32_t pack_h2(float a, float b) {
    __half2 h = __floats2half2_rn(a, b);
    return *(uint32_t*)&h;
}
__device__ __forceinline__ uint32_t f2tf32(float f) {
    uint32_t r;
    asm("cvt.rna.tf32.f32 %0, %1;" : "=r"(r) : "f"(f));
    return r;
}
__device__ __forceinline__ double dwarpsum(double v) {
#pragma unroll
    for (int o = 16; o > 0; o >>= 1) v += __shfl_xor_sync(0xffffffffu, v, o);
    return v;
}

// ---------------- merged prep: zeros + weight converts + x->half ----------------
__global__ void __launch_bounds__(256) prep_kernel(
    const float* __restrict__ prop_W, const float* __restrict__ W_proj,
    const float* __restrict__ pos_W1, const float* __restrict__ x)
{
    int gid = blockIdx.x * 256 + threadIdx.x;
    int stride = gridDim.x * 256;
    for (int i = gid; i < 3 * DIM * 5; i += stride) g_ch[i] = 0.0;
    if (gid < 3) g_Sm3[gid] = 0.0;
    if (gid < 6) g_SM33[gid] = 0.0;
    if (gid == 0) { g_sumdist = 0.0; g_maxbits = 0; }
    for (int i = gid; i < 192 * 192; i += stride) {
        int k = i / 192, n = i % 192;
        g_Wh[OFF_PROP + n * 192 + k] = __float2half(prop_W[i]);
        g_Wh[OFF_PROJ + n * 192 + k] = __float2half(W_proj[i]);
    }
    for (int i = gid; i < 48 * 576; i += stride) {
        int k = i / 576, n = i % 576;
        int m = n / 192, c = n % 192;
        g_W1t[i] = f2tf32(pos_W1[((long)m * 48 + k) * 192 + c]);
    }
    for (int i = gid; i < NPTS * DIM / 2; i += stride) {
        float2 v = ((const float2*)x)[i];
        ((uint32_t*)g_xh)[i] = pack_h2(v.x, v.y);
    }
}

// ---------------- merged tiny precompute ----------------
__global__ void __launch_bounds__(192) small_kernel(
    const float* __restrict__ de_W2, const float* __restrict__ de_b2,
    const float* __restrict__ kp_W, const float* __restrict__ kp_b,
    const float* __restrict__ fus_b, const float* __restrict__ W_qkv)
{
    int b = blockIdx.x, t = threadIdx.x;
    if (b == 0) {
        if (t < DQ) {
            float s = 0.f;
            for (int c = 0; c < DIM; c++) s += de_W2[t * DIM + c] * kp_W[c];
            g_kpwproj[t] = s;
        }
        if (t == 63) {
            float s = 0.f;
            for (int c = 0; c < DIM; c++) s += de_b2[c] * kp_W[c];
            g_kpconst = s + kp_b[0];
        }
    } else {
        int n = (b - 1) * 192 + t;
        if (n < 576) {
            float s = 0.f;
            for (int j = 0; j < 192; j++) s += fus_b[j] * W_qkv[j * 576 + n];
            g_bfq[n] = s;
        }
    }
}

// ---------------- pos_W2 -> fragment table (mat 2 pv usage) ----------------
__global__ void __launch_bounds__(256) w2f_kernel(const float* __restrict__ pos_W2) {
    int gid = blockIdx.x * 256 + threadIdx.x;
    if (gid >= 55296) return;
    int e = gid & 3;
    int r = gid >> 2;
    int lane = r & 31; r >>= 5;
    int qq = r % 3; r /= 3;
    int ks = r % 12; r /= 12;
    int wn = r & 3;
    int m = r >> 2;
    int q = qq * 4 + e;
    int nt = q >> 1, ib = q & 1;
    int g = lane >> 2, la3 = lane & 3;
    int nr = 48 * wn + 8 * nt + g;
    int o = ks * 8 + la3 + 4 * ib;
    const float* W2m = pos_W2 + (long)m * DIM * DIM;
    g_W2f[gid] = pack_h2(W2m[(2 * o) * DIM + nr], W2m[(2 * o + 1) * DIM + nr]);
}

// ---------------- W2^T fragments for per-block U-mma (mats 0,1) ----------------
__global__ void __launch_bounds__(256) w2u_kernel(const float* __restrict__ pos_W2) {
    int gid = blockIdx.x * 256 + threadIdx.x;
    if (gid >= 36864) return;
    int e = gid & 1;
    int r = gid >> 1;
    int lane = r & 31; r >>= 5;
    int ks = r & 1; r >>= 1;
    int nt = r % 24; r /= 24;
    int h = r % 6;
    int m = r / 6;                  // 0..1
    int g = lane >> 2, la3 = lane & 3;
    int nr = 8 * nt + g;            // output k index 0..191
    int cl = 16 * ks + 8 * e + 2 * la3;
    int cout = 32 * h + cl;
    const float* W2m = pos_W2 + (long)m * DIM * DIM;
    ((uint32_t*)g_W2u)[((((m * 6 + h) * 24 + nt) * 2 + ks) * 32 + lane) * 2 + e] =
        pack_h2(W2m[nr * DIM + cout], W2m[nr * DIM + cout + 1]);
}

// ---------------- Wfq = fus_W @ W_qkv : 32x32 tiles ----------------
__global__ void __launch_bounds__(256) wfq_kernel(const float* __restrict__ fus_W,
                                                  const float* __restrict__ W_qkv) {
    __shared__ float As[16][33];
    __shared__ float Bs[16][33];
    int t = threadIdx.x;
    int row0 = blockIdx.y * 32;
    int col0 = blockIdx.x * 32;
    int rg = t / 16, cg = t % 16;
    int a_k = t % 16, a_m = t / 16;
    float acc[2][2] = {};
    for (int k0 = 0; k0 < 192; k0 += 16) {
#pragma unroll
        for (int p = 0; p < 2; p++)
            As[a_k][a_m + p * 16] = fus_W[(row0 + a_m + p * 16) * 192 + k0 + a_k];
#pragma unroll
        for (int p = 0; p < 2; p++) {
            int u = t + p * 256;
            int kk = u >> 5, n = u & 31;
            Bs[kk][n] = W_qkv[(k0 + kk) * 576 + col0 + n];
        }
        __syncthreads();
#pragma unroll
        for (int kk = 0; kk < 16; kk++) {
            float a0 = As[kk][rg * 2], a1 = As[kk][rg * 2 + 1];
            float b0 = Bs[kk][cg * 2], b1 = Bs[kk][cg * 2 + 1];
            acc[0][0] += a0 * b0; acc[0][1] += a0 * b1;
            acc[1][0] += a1 * b0; acc[1][1] += a1 * b1;
        }
        __syncthreads();
    }
#pragma unroll
    for (int i = 0; i < 2; i++)
#pragma unroll
        for (int j = 0; j < 2; j++)
            g_Wh[OFF_QKV + (col0 + cg * 2 + j) * 192 + row0 + rg * 2 + i] = __float2half(acc[i][j]);
}

// ---------------- fp16 tensor-core GEMM ----------------
__global__ void __launch_bounds__(256) hgemm_kernel(
    const __half* __restrict__ Ah, int woff, const float* __restrict__ bias,
    const float* __restrict__ addvec, float* __restrict__ C, int Ncol)
{
    __shared__ uint32_t sA[128][36];
    __shared__ uint32_t sB[64][36];
    int t = threadIdx.x;
    int wid = t >> 5, lane = t & 31;
    int wm = wid & 3, wn = wid >> 2;
    int g = lane >> 2, la3 = lane & 3;
    int row0 = blockIdx.y * 128, col0 = blockIdx.x * 64;
    const uint32_t* Whu = (const uint32_t*)(g_Wh + woff);
    const uint32_t* Au = (const uint32_t*)Ah;
    uint32_t sAb = (uint32_t)__cvta_generic_to_shared(&sA[0][0]);
    uint32_t sBb = (uint32_t)__cvta_generic_to_shared(&sB[0][0]);
    float acc[2][4][4] = {};
    for (int kp = 0; kp < 3; kp++) {
        int k0 = kp * 64;
        for (int u = t; u < 4096; u += 256) {
            int r = u >> 5, cu = u & 31;
            uint32_t v = Au[(long)(row0 + r) * 96 + (k0 >> 1) + cu];
            if (addvec) {
                float2 f = __half22float2(*(__half2*)&v);
                f.x += addvec[k0 + 2 * cu];
                f.y += addvec[k0 + 2 * cu + 1];
                v = pack_h2(f.x, f.y);
            }
            sA[r][cu] = v;
        }
        for (int u = t; u < 2048; u += 256) {
            int r = u >> 5, cu = u & 31;
            sB[r][cu] = Whu[(col0 + r) * 96 + (k0 >> 1) + cu];
        }
        __syncthreads();
#pragma unroll
        for (int ks = 0; ks < 4; ks++) {
            uint32_t afr[2][4], bfr[2][4];
#pragma unroll
            for (int mt = 0; mt < 2; mt++) {
                uint32_t addr = sAb + 4 * ((32 * wm + 16 * mt + (lane & 15)) * 36
                                           + ks * 8 + (lane >> 4) * 4);
                ldm_x4(afr[mt], addr);
            }
#pragma unroll
            for (int p = 0; p < 2; p++) {
                uint32_t addr = sBb + 4 * ((32 * wn + 16 * p + (lane >> 4) * 8 + (lane & 7)) * 36
                                           + ks * 8 + ((lane >> 3) & 1) * 4);
                ldm_x4(bfr[p], addr);
            }
#pragma unroll
            for (int nt = 0; nt < 4; nt++) {
                int p = nt >> 1, i0 = (nt & 1) * 2;
                mma_f16(acc[0][nt], afr[0], bfr[p][i0], bfr[p][i0 + 1]);
                mma_f16(acc[1][nt], afr[1], bfr[p][i0], bfr[p][i0 + 1]);
            }
        }
        __syncthreads();
    }
#pragma unroll
    for (int mt = 0; mt < 2; mt++) {
#pragma unroll
        for (int nt = 0; nt < 4; nt++) {
            int col = col0 + 32 * wn + 8 * nt + 2 * la3;
            float b0v = bias ? bias[col] : 0.f;
            float b1v = bias ? bias[col + 1] : 0.f;
            int r = row0 + 32 * wm + 16 * mt + g;
            *(float2*)&C[(long)r * Ncol + col] =
                make_float2(acc[mt][nt][0] + b0v, acc[mt][nt][1] + b1v);
            *(float2*)&C[(long)(r + 8) * Ncol + col] =
                make_float2(acc[mt][nt][2] + b0v, acc[mt][nt][3] + b1v);
        }
    }
}

// ---------------- A = knnxyz @ pos_W1 + pos_b1 via tf32 mma (K=48) ----------------
__global__ void __launch_bounds__(256) agemm_kernel(const float* __restrict__ pos_b1) {
    __shared__ uint32_t sA[128 * 50];
    __shared__ uint32_t sB[48 * 72];
    int t = threadIdx.x;
    int wid = t >> 5, lane = t & 31;
    int wm = wid & 3, wn = wid >> 2;
    int g = lane >> 2, la3 = lane & 3;
    int row0 = blockIdx.y * 128, col0 = blockIdx.x * 64;
    int m_blk = col0 / 192, cbase = col0 - m_blk * 192;

    for (int u = t; u < 128 * 48; u += 256) {
        int r = u / 48, k = u % 48;
        sA[r * 50 + k] = f2tf32(g_knnxyz[(long)(row0 + r) * 48 + k]);
    }
    for (int u = t; u < 48 * 64; u += 256) {
        int k = u >> 6, n = u & 63;
        sB[k * 72 + n] = g_W1t[k * 576 + col0 + n];
    }
    __syncthreads();

    float acc[2][4][4] = {};
#pragma unroll
    for (int ks = 0; ks < 6; ks++) {
        int ca = ks * 8 + la3;
        uint32_t afr[2][4];
#pragma unroll
        for (int mt = 0; mt < 2; mt++) {
            int r = 32 * wm + 16 * mt + g;
            afr[mt][0] = sA[r * 50 + ca];
            afr[mt][1] = sA[(r + 8) * 50 + ca];
            afr[mt][2] = sA[r * 50 + ca + 4];
            afr[mt][3] = sA[(r + 8) * 50 + ca + 4];
        }
#pragma unroll
        for (int nt = 0; nt < 4; nt++) {
            int nc = 32 * wn + 8 * nt + g;
            uint32_t b0 = sB[ca * 72 + nc];
            uint32_t b1 = sB[(ca + 4) * 72 + nc];
            mma_tf32(acc[0][nt], afr[0], b0, b1);
            mma_tf32(acc[1][nt], afr[1], b0, b1);
        }
    }
#pragma unroll
    for (int mt = 0; mt < 2; mt++) {
#pragma unroll
        for (int nt = 0; nt < 4; nt++) {
            int colL = 32 * wn + 8 * nt + 2 * la3;
            float b0v = pos_b1[col0 + colL], b1v = pos_b1[col0 + colL + 1];
            int r = row0 + 32 * wm + 16 * mt + g;
            *(float2*)&g_A[((long)m_blk * NPTS + r) * DIM + cbase + colL] =
                make_float2(acc[mt][nt][0] + b0v, acc[mt][nt][1] + b1v);
            *(float2*)&g_A[((long)m_blk * NPTS + r + 8) * DIM + cbase + colL] =
                make_float2(acc[mt][nt][2] + b0v, acc[mt][nt][3] + b1v);
        }
    }
}

// ---------------- per-node stage 1 ----------------
__global__ void __launch_bounds__(192) node1_kernel(
    const float* __restrict__ p, const float* __restrict__ x, const int* __restrict__ knn,
    const float* __restrict__ prop_W, const float* __restrict__ prop_b,
    const float* __restrict__ gA_W, const float* __restrict__ gA_b,
    const float* __restrict__ gB_W, const float* __restrict__ gB_b,
    const float* __restrict__ kn, const float* __restrict__ de_W1,
    const float* __restrict__ de_b1, const float* __restrict__ de_W2,
    const float* __restrict__ de_b2)
{
    int n = blockIdx.x;
    int c = threadIdx.x;
    __shared__ float s_p[3];
    __shared__ int   s_idx[NS];
    __shared__ float s_xyz[NS * 3];
    __shared__ float s_pr[NS * 3];
    __shared__ float s_dist[NS];
    __shared__ float s_rep[9];
    __shared__ float s_maxd;
    __shared__ float s_kd[KSP];
    __shared__ float s_g[KSP * DQ];
    __shared__ float s_sc[KSP];
    __shared__ float s_w[DQ];

    if (c < 3) s_p[c] = p[n * 3 + c];
    if (c < NS) s_idx[c] = knn[n * NS + c];
    __syncthreads();

    if (c < NS) {
        int id = s_idx[c];
        float ax = p[id * 3 + 0], ay = p[id * 3 + 1], az = p[id * 3 + 2];
        s_xyz[c * 3 + 0] = ax; s_xyz[c * 3 + 1] = ay; s_xyz[c * 3 + 2] = az;
        float rx = ax - s_p[0], ry = ay - s_p[1], rz = az - s_p[2];
        s_pr[c * 3 + 0] = rx; s_pr[c * 3 + 1] = ry; s_pr[c * 3 + 2] = rz;
        s_dist[c] = sqrtf(rx * rx + ry * ry + rz * rz + 1e-12f);
    }
    if (c >= 32 && c < 32 + KSP) {
        int s = c - 32;
        float dx = s_p[0] - kn[s * 3 + 0];
        float dy = s_p[1] - kn[s * 3 + 1];
        float dz = s_p[2] - kn[s * 3 + 2];
        s_kd[s] = sqrtf(dx * dx + dy * dy + dz * dz + 1e-12f);
    }
    __syncthreads();

    if (c == 0) {
        float mx = 0, my = 0, mz = 0, qx = 0, qy = 0, qz = 0, md = 0, sd = 0;
        for (int j = 0; j < NS; j++) {
            mx += s_pr[j * 3]; my += s_pr[j * 3 + 1]; mz += s_pr[j * 3 + 2];
            qx += s_xyz[j * 3]; qy += s_xyz[j * 3 + 1]; qz += s_xyz[j * 3 + 2];
            md = fmaxf(md, s_dist[j]); sd += s_dist[j];
        }
        const float inv = 1.f / NS;
        s_rep[0] = mx * inv; s_rep[1] = my * inv; s_rep[2] = mz * inv;
        s_rep[3] = qx * inv; s_rep[4] = qy * inv; s_rep[5] = qz * inv;
        s_rep[6] = s_p[0]; s_rep[7] = s_p[1]; s_rep[8] = s_p[2];
        s_maxd = md;
        g_distsum[n] = sd; g_distmax[n] = md;
        g_m3[n * 3 + 0] = qx; g_m3[n * 3 + 1] = qy; g_m3[n * 3 + 2] = qz;
    }
    if (c < NS * 3) g_knnxyz[n * 48 + c] = s_xyz[c];
    for (int idx = c; idx < KSP * DQ; idx += 192) {
        int s = idx / DQ, k = idx % DQ;
        s_g[idx] = fmaxf(s_kd[s] * de_W1[k] + de_b1[k], 0.f);
    }
    __syncthreads();

    if (c < KSP) {
        float l = g_kpconst;
        for (int k = 0; k < DQ; k++) l += s_g[c * DQ + k] * g_kpwproj[k];
        s_sc[c] = l;
    }
    __syncthreads();
    if (c == 0) {
        float mx = -1e30f;
        for (int s = 0; s < KSP; s++) mx = fmaxf(mx, s_sc[s]);
        float se = 0.f;
        for (int s = 0; s < KSP; s++) { float e = expf(s_sc[s] - mx); s_sc[s] = e; se += e; }
        float inv = 1.f / se;
        for (int s = 0; s < KSP; s++) s_sc[s] *= inv;
    }
    __syncthreads();
    if (c < DQ) {
        float w = 0.f;
        for (int s = 0; s < KSP; s++) w += s_sc[s] * s_g[s * DQ + c];
        s_w[c] = w;
    }
    __syncthreads();

    float dist_feat = de_b2[c];
#pragma unroll
    for (int k = 0; k < DQ; k++) dist_feat += s_w[k] * de_W2[k * DIM + c];

    float geo = gA_b[c] + gB_b[c] + s_maxd * gB_W[c];
#pragma unroll
    for (int i = 0; i < 9; i++) geo += s_rep[i] * gA_W[i * DIM + c];

    float w0 = prop_W[192 * DIM + c], w1 = prop_W[193 * DIM + c], w2 = prop_W[194 * DIM + c];
    float pb = prop_b[c];
    float msg = 0.f;
#pragma unroll
    for (int s = 0; s < NS; s++) {
        float v = g_xpw[(long)s_idx[s] * DIM + c]
                + s_pr[s * 3] * w0 + s_pr[s * 3 + 1] * w1 + s_pr[s * 3 + 2] * w2 + pb;
        msg += fmaxf(v, 0.f);
    }
    msg *= (1.f / NS);
    g_prefh[(long)n * DIM + c] = __float2half(x[(long)n * DIM + c] + msg + geo + dist_feat);
}

// ---------------- global reductions ----------------
__global__ void __launch_bounds__(256) reduce_kernel() {
    int tid = blockIdx.x * blockDim.x + threadIdx.x;
    int stride = gridDim.x * blockDim.x;
    double lsum = 0, l0 = 0, l1 = 0, l2 = 0;
    float lmax = 0.f;
    for (int n = tid; n < NPTS; n += stride) {
        lsum += (double)g_distsum[n];
        lmax = fmaxf(lmax, g_distmax[n]);
        l0 += (double)g_m3[n * 3 + 0];
        l1 += (double)g_m3[n * 3 + 1];
        l2 += (double)g_m3[n * 3 + 2];
    }
    double m0 = 0, m1 = 0, m2 = 0, m3v = 0, m4 = 0, m5 = 0;
    for (int idx = tid; idx < NPTS * NS; idx += stride) {
        float xx = g_knnxyz[idx * 3 + 0];
        float yy = g_knnxyz[idx * 3 + 1];
        float zz = g_knnxyz[idx * 3 + 2];
        m0 += (double)xx * xx; m1 += (double)xx * yy; m2 += (double)xx * zz;
        m3v += (double)yy * yy; m4 += (double)yy * zz; m5 += (double)zz * zz;
    }
    lsum = dwarpsum(lsum); l0 = dwarpsum(l0); l1 = dwarpsum(l1); l2 = dwarpsum(l2);
    m0 = dwarpsum(m0); m1 = dwarpsum(m1); m2 = dwarpsum(m2);
    m3v = dwarpsum(m3v); m4 = dwarpsum(m4); m5 = dwarpsum(m5);
#pragma unroll
    for (int o = 16; o > 0; o >>= 1) lmax = fmaxf(lmax, __shfl_xor_sync(0xffffffffu, lmax, o));
    if ((threadIdx.x & 31) == 0) {
        atomicAdd(&g_sumdist, lsum);
        atomicAdd(&g_Sm3[0], l0); atomicAdd(&g_Sm3[1], l1); atomicAdd(&g_Sm3[2], l2);
        atomicAdd(&g_SM33[0], m0); atomicAdd(&g_SM33[1], m1); atomicAdd(&g_SM33[2], m2);
        atomicAdd(&g_SM33[3], m3v); atomicAdd(&g_SM33[4], m4); atomicAdd(&g_SM33[5], m5);
        atomicMax(&g_maxbits, __float_as_int(lmax));
    }
}

// ---------------- BN per-channel statistics ----------------
#define BNCHUNK 64
__global__ void __launch_bounds__(192) bnstats_kernel() {
    int m = blockIdx.y;
    int n0 = blockIdx.x * BNCHUNK;
    int c = threadIdx.x;
    float sa = 0, sa2 = 0, sx = 0, sy = 0, sz = 0;
    const float* Abase = g_A + (long)m * NPTS * DIM;
    for (int n = n0; n < n0 + BNCHUNK; n++) {
        float a = Abase[(long)n * DIM + c];
        float mx = g_m3[n * 3 + 0], my = g_m3[n * 3 + 1], mz = g_m3[n * 3 + 2];
        sa += a;
        sa2 += a * a;
        sx += a * mx; sy += a * my; sz += a * mz;
    }
    double* d = g_ch + ((long)m * DIM + c) * 5;
    atomicAdd(d + 0, (double)sa); atomicAdd(d + 1, (double)sa2);
    atomicAdd(d + 2, (double)sx); atomicAdd(d + 3, (double)sy); atomicAdd(d + 4, (double)sz);
}

// ---------------- finalize ----------------
__global__ void __launch_bounds__(192) finalize_kernel(
    const float* __restrict__ pos_W1, const float* __restrict__ pos_gamma,
    const float* __restrict__ pos_beta, const float* __restrict__ gC_W,
    const float* __restrict__ gC_b)
{
    int c = threadIdx.x;
    float Sv[3][3];
#pragma unroll
    for (int m = 0; m < 3; m++)
#pragma unroll
        for (int k = 0; k < 3; k++) {
            float s = 0.f;
            for (int j = 0; j < NS; j++) s += pos_W1[(long)m * 48 * DIM + (3 * j + k) * DIM + c];
            Sv[m][k] = s;
            g_S[(m * 3 + k) * DIM + c] = s;
        }
    const double T = (double)NPTS * NS;
    double Q0 = g_SM33[0], Q1 = g_SM33[1], Q2 = g_SM33[2], Q3 = g_SM33[3], Q4 = g_SM33[4], Q5 = g_SM33[5];
    double P0 = g_Sm3[0], P1 = g_Sm3[1], P2 = g_Sm3[2];
#pragma unroll
    for (int m = 0; m < 3; m++) {
        const double* d = g_ch + ((long)m * DIM + c) * 5;
        double SA = d[0], SA2 = d[1], SMx = d[2], SMy = d[3], SMz = d[4];
        double Sx = Sv[m][0], Sy = Sv[m][1], Sz = Sv[m][2];
        double mean = (16.0 * SA - (Sx * P0 + Sy * P1 + Sz * P2)) / T;
        double sq = 16.0 * SA2 - 2.0 * (Sx * SMx + Sy * SMy + Sz * SMz)
                  + Sx * Sx * Q0 + Sy * Sy * Q3 + Sz * Sz * Q5
                  + 2.0 * (Sx * Sy * Q1 + Sx * Sz * Q2 + Sy * Sz * Q4);
        double var = sq / T - mean * mean;
        float sc = pos_gamma[m * DIM + c] * rsqrtf((float)(var + 1e-5));
        g_bnscale[m * DIM + c] = sc;
        g_bnshift[m * DIM + c] = pos_beta[m * DIM + c] - (float)mean * sc;
    }
    float maxd = __int_as_float(g_maxbits);
    float vol = (float)(g_sumdist / T) / (maxd + 1e-8f);
    g_volvec[c] = vol * gC_W[c] + gC_b[c];
}

// ---------------- fused attention: 4 nodes / 256 threads / occupancy 2 ----------------
#define SH_OFF    0          // 2 x 64 x 100 u32 = 51200 (h mats 0,1; buf 0 reused for mat 2)
#define SU_OFF    51200      // U [2][4][6][96] u32 = 18432
#define SQ_OFF    69632      // q0 f32 4x192 = 3072
#define SK_OFF    72704      // 3072
#define SQH_OFF   75776      // q0 h2 [16][100] = 6400
#define SKH_OFF   82176      // 6400
#define SB2_OFF   88576      // 2304
#define SSC_OFF   90880      // 4x6x16 f32 = 1536
#define SWT_OFF   92416      // 1536
#define SXYZ_OFF  93952      // 768
#define SIDX_OFF  94720      // 256
#define SAH_OFF   94976      // 3x4x192 f32 = 9216
#define SSH_OFF   104192     // 6912
#define ATT_SMEM  111104

__global__ void __launch_bounds__(256, 2) attn_mma_kernel(
    const int* __restrict__ knn, const float* __restrict__ pos_b2)
{
    extern __shared__ char smem[];
    const int t = threadIdx.x;
    const int wid = t >> 5, lane = t & 31;
    const int g = lane >> 2, la3 = lane & 3;
    const int nb = blockIdx.x * 4;

    uint32_t* s_h  = (uint32_t*)(smem + SH_OFF);
    uint32_t* s_u  = (uint32_t*)(smem + SU_OFF);
    float* s_q   = (float*)(smem + SQ_OFF);
    float* s_k0  = (float*)(smem + SK_OFF);
    uint32_t* s_qh = (uint32_t*)(smem + SQH_OFF);
    uint32_t* s_kh = (uint32_t*)(smem + SKH_OFF);
    float* s_b2  = (float*)(smem + SB2_OFF);
    float* s_sc  = (float*)(smem + SSC_OFF);
    float* s_w   = (float*)(smem + SWT_OFF);
    float* s_xyz = (float*)(smem + SXYZ_OFF);
    int*   s_idx = (int*)(smem + SIDX_OFF);
    float* s_ahat = (float*)(smem + SAH_OFF);
    float* s_Sh   = (float*)(smem + SSH_OFF);
    const uint32_t shb  = (uint32_t)__cvta_generic_to_shared(smem + SH_OFF);
    const uint32_t sqhb = (uint32_t)__cvta_generic_to_shared(smem + SQH_OFF);
    const uint32_t skhb = (uint32_t)__cvta_generic_to_shared(smem + SKH_OFF);

    const int grow = t >> 2;               // 0..63
    const int gn2 = grow >> 4, gj2 = grow & 15;

    // ---- phase A: stage shared inputs ----
    for (int u = t; u < 64; u += 256) s_idx[u] = knn[(nb + (u >> 4)) * NS + (u & 15)];
    for (int u = t; u < 4 * 48; u += 256) s_xyz[u] = g_knnxyz[(long)nb * 48 + u];
    for (int u = t; u < 3 * DIM; u += 256) s_b2[u] = pos_b2[u];
    for (int u = t; u < 4 * DIM; u += 256) {
        int n = u / DIM, c = u % DIM;
        long r0 = (long)knn[(nb + n) * NS] * 576;
        s_q[u]  = g_qkv[r0 + c];
        s_k0[u] = g_qkv[r0 + 192 + c];
    }
    for (int u = t; u < 3 * 4 * DIM; u += 256) {
        int m = u / (4 * DIM);
        int rem = u - m * 4 * DIM;
        int node = rem / DIM, cg = rem % DIM;
        float a = g_A[((long)m * NPTS + nb + node) * DIM + cg];
        s_ahat[u] = a * g_bnscale[m * DIM + cg] + g_bnshift[m * DIM + cg];
    }
    for (int u = t; u < 3 * 3 * DIM; u += 256) {
        int m = u / (3 * DIM);
        int rem = u - m * 3 * DIM;
        s_Sh[u] = g_S[(m * 3 + rem / DIM) * DIM + (rem % DIM)] * g_bnscale[m * DIM + rem % DIM];
    }
    __syncthreads();

    // ---- phase B: base scores + gen h (mats 0,1) + fp16 q0/k0 staging ----
    for (int task = t; task < 384; task += 256) {
        int n = task / 96, h = (task / 16) % 6, j = task & 15;
        const float4* qv = (const float4*)(s_q + n * DIM + 32 * h);
        const float4* kv0 = (const float4*)(s_k0 + n * DIM + 32 * h);
        const float4* b0 = (const float4*)(s_b2 + 32 * h);
        const float4* b1 = (const float4*)(s_b2 + DIM + 32 * h);
        const float4* kj = (const float4*)(g_qkv + (long)s_idx[n * 16 + j] * 576 + 192 + 32 * h);
        float dot = 0.f;
#pragma unroll
        for (int u = 0; u < 8; u++) {
            float4 q4 = qv[u], k4 = kj[u], b04 = b0[u], b14 = b1[u], kk0 = kv0[u];
            dot += q4.x * (k4.x + b04.x) + q4.y * (k4.y + b04.y)
                 + q4.z * (k4.z + b04.z) + q4.w * (k4.w + b04.w);
            dot += kk0.x * b14.x + kk0.y * b14.y + kk0.z * b14.z + kk0.w * b14.w;
        }
        s_sc[(n * 6 + h) * 16 + j] = dot;
    }
    {
        float xx = s_xyz[gn2 * 48 + gj2 * 3 + 0];
        float yy = s_xyz[gn2 * 48 + gj2 * 3 + 1];
        float zz = s_xyz[gn2 * 48 + gj2 * 3 + 2];
#pragma unroll
        for (int m = 0; m < 2; m++) {
            const float* ah = s_ahat + m * 4 * DIM + gn2 * DIM;
            const float* Sh = s_Sh + m * 3 * DIM;
            uint32_t* hdst = s_h + m * 6400 + grow * 100;
#pragma unroll
            for (int i = 0; i < 24; i++) {
                int cu = (t & 3) + 4 * i;
                int cg = 2 * cu;
                float2 a2 = *(const float2*)&ah[cg];
                float2 S0 = *(const float2*)&Sh[cg];
                float2 S1 = *(const float2*)&Sh[DIM + cg];
                float2 S2 = *(const float2*)&Sh[2 * DIM + cg];
                float h0 = a2.x - (xx * S0.x + yy * S1.x + zz * S2.x);
                float h1 = a2.y - (xx * S0.y + yy * S1.y + zz * S2.y);
                hdst[cu] = pack_h2(fmaxf(h0, 0.f), fmaxf(h1, 0.f));
            }
        }
    }
    for (int u = t; u < 1600; u += 256) {
        int row = u / 100, cu = u % 100;
        uint32_t vq = 0, vk = 0;
        if (row < 4 && cu < 96) {
            vq = pack_h2(s_q[row * DIM + 2 * cu], s_q[row * DIM + 2 * cu + 1]);
            vk = pack_h2(s_k0[row * DIM + 2 * cu], s_k0[row * DIM + 2 * cu + 1]);
        }
        s_qh[u] = vq;
        s_kh[u] = vk;
    }
    __syncthreads();

    // ---- phase C: U-mma (8 warps loop over 12 tasks) ----
    for (int task = wid; task < 12; task += 8) {
        int m = task / 6, hh = task % 6;
        uint32_t xb = (m == 0) ? sqhb : skhb;
        const uint2* wt = g_W2u + ((m * 6 + hh) * 24) * 64;
#pragma unroll 4
        for (int nt = 0; nt < 24; nt++) {
            float acc[4] = {0.f, 0.f, 0.f, 0.f};
#pragma unroll
            for (int ks = 0; ks < 2; ks++) {
                uint32_t afr[4];
                ldm_x4(afr, xb + 4 * ((lane & 15) * 100 + 16 * hh + ks * 8 + (lane >> 4) * 4));
                uint2 bb = wt[(nt * 2 + ks) * 32 + lane];
                mma_f16(acc, afr, bb.x, bb.y);
            }
            if (g < 4)
                s_u[((m * 4 + g) * 6 + hh) * 96 + 4 * nt + la3] = pack_h2(acc[0], acc[1]);
        }
    }
    __syncthreads();

    // ---- phase C2: score-mma (8 warps): [16j x 8h] K=192 per (mat,node) ----
    {
        int m = wid >> 2, n = wid & 3;
        float acc[4] = {0.f, 0.f, 0.f, 0.f};
        const uint32_t* ub = s_u + (m * 4 + n) * 6 * 96;
#pragma unroll
        for (int ks = 0; ks < 12; ks++) {
            uint32_t afr[4];
            ldm_x4(afr, shb + 4 * (m * 6400 + (n * 16 + (lane & 15)) * 100 + ks * 8 + (lane >> 4) * 4));
            uint32_t b0 = 0, b1 = 0;
            if (g < 6) {
                b0 = ub[g * 96 + ks * 8 + la3];
                b1 = ub[g * 96 + ks * 8 + la3 + 4];
            }
            mma_f16(acc, afr, b0, b1);
        }
        int h0 = 2 * la3;
        if (h0 < 6) {
            atomicAdd(&s_sc[(n * 6 + h0) * 16 + g], acc[0]);
            atomicAdd(&s_sc[(n * 6 + h0) * 16 + g + 8], acc[2]);
        }
        if (h0 + 1 < 6) {
            atomicAdd(&s_sc[(n * 6 + h0 + 1) * 16 + g], acc[1]);
            atomicAdd(&s_sc[(n * 6 + h0 + 1) * 16 + g + 8], acc[3]);
        }
    }
    __syncthreads();

    // ---- phase D: softmax + gen h mat 2 (into buffer 0) ----
    {
        float xx = s_xyz[gn2 * 48 + gj2 * 3 + 0];
        float yy = s_xyz[gn2 * 48 + gj2 * 3 + 1];
        float zz = s_xyz[gn2 * 48 + gj2 * 3 + 2];
        const float* ah = s_ahat + 2 * 4 * DIM + gn2 * DIM;
        const float* Sh = s_Sh + 2 * 3 * DIM;
        uint32_t* hdst = s_h + grow * 100;
#pragma unroll
        for (int i = 0; i < 24; i++) {
            int cu = (t & 3) + 4 * i;
            int cg = 2 * cu;
            float2 a2 = *(const float2*)&ah[cg];
            float2 S0 = *(const float2*)&Sh[cg];
            float2 S1 = *(const float2*)&Sh[DIM + cg];
            float2 S2 = *(const float2*)&Sh[2 * DIM + cg];
            float h0 = a2.x - (xx * S0.x + yy * S1.x + zz * S2.x);
            float h1 = a2.y - (xx * S0.y + yy * S1.y + zz * S2.y);
            hdst[cu] = pack_h2(fmaxf(h0, 0.f), fmaxf(h1, 0.f));
        }
    }
    if (t < 24) {
        const float scale = 0.17677669529663687f;  // 32^-0.5
        float* sc = s_sc + t * 16;
        float mx = -1e30f;
#pragma unroll
        for (int j = 0; j < 16; j++) mx = fmaxf(mx, sc[j]);
        float se = 0.f;
        float ev[16];
#pragma unroll
        for (int j = 0; j < 16; j++) { ev[j] = expf((sc[j] - mx) * scale); se += ev[j]; }
        float inv = 1.f / se;
#pragma unroll
        for (int j = 0; j < 16; j++) s_w[t * 16 + j] = ev[j] * inv;
    }
    __syncthreads();

    // ---- phase E: pv-mma (8 warps) + output epilogue ----
    {
        const int wm = wid & 1, wn = wid >> 1;
        float acc[2][6][4];
#pragma unroll
        for (int a1 = 0; a1 < 2; a1++)
#pragma unroll
            for (int a2 = 0; a2 < 6; a2++)
#pragma unroll
                for (int a3 = 0; a3 < 4; a3++) acc[a1][a2][a3] = 0.f;

#pragma unroll
        for (int ks = 0; ks < 12; ks++) {
            const uint4* bq = (const uint4*)g_W2f + (((2 * 4 + wn) * 12 + ks) * 3) * 32;
            uint4 u0 = bq[lane];
            uint4 u1 = bq[32 + lane];
            uint4 u2 = bq[64 + lane];
            uint32_t afr[2][4];
#pragma unroll
            for (int mt = 0; mt < 2; mt++) {
                uint32_t addr = shb + 4 * ((32 * wm + 16 * mt + (lane & 15)) * 100
                                           + ks * 8 + (lane >> 4) * 4);
                ldm_x4(afr[mt], addr);
            }
            mma_f16(acc[0][0], afr[0], u0.x, u0.y);
            mma_f16(acc[1][0], afr[1], u0.x, u0.y);
            mma_f16(acc[0][1], afr[0], u0.z, u0.w);
            mma_f16(acc[1][1], afr[1], u0.z, u0.w);
            mma_f16(acc[0][2], afr[0], u1.x, u1.y);
            mma_f16(acc[1][2], afr[1], u1.x, u1.y);
            mma_f16(acc[0][3], afr[0], u1.z, u1.w);
            mma_f16(acc[1][3], afr[1], u1.z, u1.w);
            mma_f16(acc[0][4], afr[0], u2.x, u2.y);
            mma_f16(acc[1][4], afr[1], u2.x, u2.y);
            mma_f16(acc[0][5], afr[0], u2.z, u2.w);
            mma_f16(acc[1][5], afr[1], u2.z, u2.w);
        }

#pragma unroll
        for (int mt = 0; mt < 2; mt++) {
            int node = 2 * wm + mt;
            int j0 = g;
            long v0b = (long)s_idx[node * 16 + j0] * 576 + 384;
            long v1b = (long)s_idx[node * 16 + j0 + 8] * 576 + 384;
#pragma unroll
            for (int nt = 0; nt < 6; nt++) {
                int c0 = 48 * wn + 8 * nt + 2 * la3;
                int h = c0 >> 5;
                float w0 = s_w[(node * 6 + h) * 16 + j0];
                float w1 = s_w[(node * 6 + h) * 16 + j0 + 8];
                float b20 = s_b2[2 * DIM + c0], b21 = s_b2[2 * DIM + c0 + 1];
                float o0 = w0 * (acc[mt][nt][0] + g_qkv[v0b + c0] + b20)
                         + w1 * (acc[mt][nt][2] + g_qkv[v1b + c0] + b20);
                float o1 = w0 * (acc[mt][nt][1] + g_qkv[v0b + c0 + 1] + b21)
                         + w1 * (acc[mt][nt][3] + g_qkv[v1b + c0 + 1] + b21);
#pragma unroll
                for (int o = 4; o < 32; o <<= 1) {
                    o0 += __shfl_xor_sync(0xffffffffu, o0, o);
                    o1 += __shfl_xor_sync(0xffffffffu, o1, o);
                }
                if (g == 0) {
                    *(uint32_t*)(g_atth + (long)(nb + node) * DIM + c0) = pack_h2(o0, o1);
                }
            }
        }
    }
}

// ---------------- host launcher ----------------
extern "C" void kernel_launch(void* const* d_in, const int* in_sizes, int n_in,
                              void* d_out, int out_size)
{
    const float* p      = (const float*)d_in[0];
    const float* x      = (const float*)d_in[1];
    const int*   knn    = (const int*)d_in[2];
    const float* W_qkv  = (const float*)d_in[3];
    const float* W_proj = (const float*)d_in[4];
    const float* b_proj = (const float*)d_in[5];
    const float* prop_W = (const float*)d_in[6];
    const float* prop_b = (const float*)d_in[7];
    const float* gA_W   = (const float*)d_in[8];
    const float* gA_b   = (const float*)d_in[9];
    const float* gB_W   = (const float*)d_in[10];
    const float* gB_b   = (const float*)d_in[11];
    const float* gC_W   = (const float*)d_in[12];
    const float* gC_b   = (const float*)d_in[13];
    const float* pos_W1 = (const float*)d_in[14];
    const float* pos_b1 = (const float*)d_in[15];
    const float* pos_gamma = (const float*)d_in[16];
    const float* pos_beta  = (const float*)d_in[17];
    const float* pos_W2 = (const float*)d_in[18];
    const float* pos_b2 = (const float*)d_in[19];
    const float* kn     = (const float*)d_in[20];
    const float* de_W1  = (const float*)d_in[21];
    const float* de_b1  = (const float*)d_in[22];
    const float* de_W2  = (const float*)d_in[23];
    const float* de_b2  = (const float*)d_in[24];
    const float* kp_W   = (const float*)d_in[25];
    const float* kp_b   = (const float*)d_in[26];
    const float* fus_W  = (const float*)d_in[27];
    const float* fus_b  = (const float*)d_in[28];
    float* out = (float*)d_out;

    float *xpw, *qkv, *volvec, *bfq;
    __half *xh, *prefh, *atth;
    cudaGetSymbolAddress((void**)&xpw, g_xpw);
    cudaGetSymbolAddress((void**)&qkv, g_qkv);
    cudaGetSymbolAddress((void**)&volvec, g_volvec);
    cudaGetSymbolAddress((void**)&bfq, g_bfq);
    cudaGetSymbolAddress((void**)&xh, g_xh);
    cudaGetSymbolAddress((void**)&prefh, g_prefh);
    cudaGetSymbolAddress((void**)&atth, g_atth);

    cudaFuncSetAttribute(attn_mma_kernel, cudaFuncAttributeMaxDynamicSharedMemorySize, ATT_SMEM);

    prep_kernel<<<512, 256>>>(prop_W, W_proj, pos_W1, x);
    small_kernel<<<4, 192>>>(de_W2, de_b2, kp_W, kp_b, fus_b, W_qkv);
    w2f_kernel<<<216, 256>>>(pos_W2);
    w2u_kernel<<<144, 256>>>(pos_W2);
    wfq_kernel<<<dim3(18, 6), 256>>>(fus_W, W_qkv);
    hgemm_kernel<<<dim3(3, 128), 256>>>(xh, OFF_PROP, nullptr, nullptr, xpw, 192);
    node1_kernel<<<NPTS, 192>>>(p, x, knn, prop_W, prop_b, gA_W, gA_b, gB_W, gB_b,
                                kn, de_W1, de_b1, de_W2, de_b2);
    agemm_kernel<<<dim3(9, 128), 256>>>(pos_b1);
    reduce_kernel<<<128, 256>>>();
    bnstats_kernel<<<dim3(NPTS / BNCHUNK, 3), 192>>>();
    finalize_kernel<<<1, 192>>>(pos_W1, pos_gamma, pos_beta, gC_W, gC_b);
    hgemm_kernel<<<dim3(9, 128), 256>>>(prefh, OFF_QKV, bfq, volvec, qkv, 576);
    attn_mma_kernel<<<NPTS / 4, 256, ATT_SMEM>>>(knn, pos_b2);
    hgemm_kernel<<<dim3(3, 128), 256>>>(atth, OFF_PROJ, b_proj, nullptr, out, 192);
}

// round 15
// speedup vs baseline: 1.1110x; 1.1110x over previous
#include <cuda_runtime.h>
#include <cuda_fp16.h>
#include <math.h>
#include <stdint.h>

#define NPTS 16384
#define DIM  192
#define NS   16
#define NH   6
#define HD   32
#define KSP  16
#define DQ   48

// ---------------- scratch (device globals; no allocs allowed) ----------------
__device__ float g_xpw[NPTS * DIM];
__device__ __half g_qkvh[NPTS * 576];      // qkv as half
__device__ float g_A[3L * NPTS * DIM];
__device__ float g_knnxyz[NPTS * 48];
__device__ float g_m3[NPTS * 3];
__device__ float g_distsum[NPTS];
__device__ float g_distmax[NPTS];
__device__ double g_ch[3 * DIM * 5];
__device__ double g_Sm3[3];
__device__ double g_SM33[6];
__device__ double g_sumdist;
__device__ int    g_maxbits;
__device__ float g_S[9 * DIM];
__device__ float g_bnscale[3 * DIM];
__device__ float g_bnshift[3 * DIM];
__device__ float g_volvec[DIM];
__device__ float g_kpwproj[DQ];
__device__ float g_kpconst;
__device__ __half g_Wh[184320];            // dense weights as half, [n][k=192]
__device__ uint32_t g_W1t[48 * 576];       // pos_W1 as tf32 bits
__device__ float g_bfq[576];               // fus_b @ W_qkv
__device__ uint32_t g_W2f[55296];          // pos_W2 fp16 mma fragments (m=2 slice used)
__device__ uint2 g_W2u[18432];             // W2^T fragments for U-mma
__device__ __half g_xh[NPTS * DIM];        // x as half
__device__ __half g_prefh[NPTS * DIM];     // prefus as half
__device__ __half g_atth[NPTS * DIM];      // attn out as half

#define OFF_PROP 0
#define OFF_QKV  36864
#define OFF_PROJ 147456

__device__ __forceinline__ void mma_f16(float* c, const uint32_t* a, uint32_t b0, uint32_t b1) {
    asm volatile("mma.sync.aligned.m16n8k16.row.col.f32.f16.f16.f32 "
        "{%0,%1,%2,%3}, {%4,%5,%6,%7}, {%8,%9}, {%0,%1,%2,%3};"
        : "+f"(c[0]), "+f"(c[1]), "+f"(c[2]), "+f"(c[3])
        : "r"(a[0]), "r"(a[1]), "r"(a[2]), "r"(a[3]), "r"(b0), "r"(b1));
}
__device__ __forceinline__ void mma_tf32(float* c, const uint32_t* a, uint32_t b0, uint32_t b1) {
    asm volatile("mma.sync.aligned.m16n8k8.row.col.f32.tf32.tf32.f32 "
        "{%0,%1,%2,%3}, {%4,%5,%6,%7}, {%8,%9}, {%0,%1,%2,%3};"
        : "+f"(c[0]), "+f"(c[1]), "+f"(c[2]), "+f"(c[3])
        : "r"(a[0]), "r"(a[1]), "r"(a[2]), "r"(a[3]), "r"(b0), "r"(b1));
}
__device__ __forceinline__ void ldm_x4(uint32_t* d, uint32_t a) {
    asm volatile("ldmatrix.sync.aligned.m8n8.x4.shared.b16 {%0,%1,%2,%3}, [%4];"
        : "=r"(d[0]), "=r"(d[1]), "=r"(d[2]), "=r"(d[3]) : "r"(a));
}
__device__ __forceinline__ uint32_t pack_h2(float a, float b) {
    __half2 h = __floats2half2_rn(a, b);
    return *(uint32_t*)&h;
}
__device__ __forceinline__ float2 up_h2(uint32_t v) {
    return __half22float2(*(__half2*)&v);
}
__device__ __forceinline__ uint32_t f2tf32(float f) {
    uint32_t r;
    asm("cvt.rna.tf32.f32 %0, %1;" : "=r"(r) : "f"(f));
    return r;
}
__device__ __forceinline__ double dwarpsum(double v) {
#pragma unroll
    for (int o = 16; o > 0; o >>= 1) v += __shfl_xor_sync(0xffffffffu, v, o);
    return v;
}

// ---------------- merged prep: zeros + weight converts + x->half ----------------
__global__ void __launch_bounds__(256) prep_kernel(
    const float* __restrict__ prop_W, const float* __restrict__ W_proj,
    const float* __restrict__ pos_W1, const float* __restrict__ x)
{
    int gid = blockIdx.x * 256 + threadIdx.x;
    int stride = gridDim.x * 256;
    for (int i = gid; i < 3 * DIM * 5; i += stride) g_ch[i] = 0.0;
    if (gid < 3) g_Sm3[gid] = 0.0;
    if (gid < 6) g_SM33[gid] = 0.0;
    if (gid == 0) { g_sumdist = 0.0; g_maxbits = 0; }
    for (int i = gid; i < 192 * 192; i += stride) {
        int k = i / 192, n = i % 192;
        g_Wh[OFF_PROP + n * 192 + k] = __float2half(prop_W[i]);
        g_Wh[OFF_PROJ + n * 192 + k] = __float2half(W_proj[i]);
    }
    for (int i = gid; i < 48 * 576; i += stride) {
        int k = i / 576, n = i % 576;
        int m = n / 192, c = n % 192;
        g_W1t[i] = f2tf32(pos_W1[((long)m * 48 + k) * 192 + c]);
    }
    for (int i = gid; i < NPTS * DIM / 2; i += stride) {
        float2 v = ((const float2*)x)[i];
        ((uint32_t*)g_xh)[i] = pack_h2(v.x, v.y);
    }
}

// ---------------- merged tiny precompute ----------------
__global__ void __launch_bounds__(192) small_kernel(
    const float* __restrict__ de_W2, const float* __restrict__ de_b2,
    const float* __restrict__ kp_W, const float* __restrict__ kp_b,
    const float* __restrict__ fus_b, const float* __restrict__ W_qkv)
{
    int b = blockIdx.x, t = threadIdx.x;
    if (b == 0) {
        if (t < DQ) {
            float s = 0.f;
            for (int c = 0; c < DIM; c++) s += de_W2[t * DIM + c] * kp_W[c];
            g_kpwproj[t] = s;
        }
        if (t == 63) {
            float s = 0.f;
            for (int c = 0; c < DIM; c++) s += de_b2[c] * kp_W[c];
            g_kpconst = s + kp_b[0];
        }
    } else {
        int n = (b - 1) * 192 + t;
        if (n < 576) {
            float s = 0.f;
            for (int j = 0; j < 192; j++) s += fus_b[j] * W_qkv[j * 576 + n];
            g_bfq[n] = s;
        }
    }
}

// ---------------- pos_W2 -> fragment table (mat 2 pv usage) ----------------
__global__ void __launch_bounds__(256) w2f_kernel(const float* __restrict__ pos_W2) {
    int gid = blockIdx.x * 256 + threadIdx.x;
    if (gid >= 55296) return;
    int e = gid & 3;
    int r = gid >> 2;
    int lane = r & 31; r >>= 5;
    int qq = r % 3; r /= 3;
    int ks = r % 12; r /= 12;
    int wn = r & 3;
    int m = r >> 2;
    int q = qq * 4 + e;
    int nt = q >> 1, ib = q & 1;
    int g = lane >> 2, la3 = lane & 3;
    int nr = 48 * wn + 8 * nt + g;
    int o = ks * 8 + la3 + 4 * ib;
    const float* W2m = pos_W2 + (long)m * DIM * DIM;
    g_W2f[gid] = pack_h2(W2m[(2 * o) * DIM + nr], W2m[(2 * o + 1) * DIM + nr]);
}

// ---------------- W2^T fragments for per-block U-mma (mats 0,1) ----------------
__global__ void __launch_bounds__(256) w2u_kernel(const float* __restrict__ pos_W2) {
    int gid = blockIdx.x * 256 + threadIdx.x;
    if (gid >= 36864) return;
    int e = gid & 1;
    int r = gid >> 1;
    int lane = r & 31; r >>= 5;
    int ks = r & 1; r >>= 1;
    int nt = r % 24; r /= 24;
    int h = r % 6;
    int m = r / 6;                  // 0..1
    int g = lane >> 2, la3 = lane & 3;
    int nr = 8 * nt + g;            // output k index 0..191
    int cl = 16 * ks + 8 * e + 2 * la3;
    int cout = 32 * h + cl;
    const float* W2m = pos_W2 + (long)m * DIM * DIM;
    ((uint32_t*)g_W2u)[((((m * 6 + h) * 24 + nt) * 2 + ks) * 32 + lane) * 2 + e] =
        pack_h2(W2m[nr * DIM + cout], W2m[nr * DIM + cout + 1]);
}

// ---------------- Wfq = fus_W @ W_qkv : 32x32 tiles ----------------
__global__ void __launch_bounds__(256) wfq_kernel(const float* __restrict__ fus_W,
                                                  const float* __restrict__ W_qkv) {
    __shared__ float As[16][33];
    __shared__ float Bs[16][33];
    int t = threadIdx.x;
    int row0 = blockIdx.y * 32;
    int col0 = blockIdx.x * 32;
    int rg = t / 16, cg = t % 16;
    int a_k = t % 16, a_m = t / 16;
    float acc[2][2] = {};
    for (int k0 = 0; k0 < 192; k0 += 16) {
#pragma unroll
        for (int p = 0; p < 2; p++)
            As[a_k][a_m + p * 16] = fus_W[(row0 + a_m + p * 16) * 192 + k0 + a_k];
#pragma unroll
        for (int p = 0; p < 2; p++) {
            int u = t + p * 256;
            int kk = u >> 5, n = u & 31;
            Bs[kk][n] = W_qkv[(k0 + kk) * 576 + col0 + n];
        }
        __syncthreads();
#pragma unroll
        for (int kk = 0; kk < 16; kk++) {
            float a0 = As[kk][rg * 2], a1 = As[kk][rg * 2 + 1];
            float b0 = Bs[kk][cg * 2], b1 = Bs[kk][cg * 2 + 1];
            acc[0][0] += a0 * b0; acc[0][1] += a0 * b1;
            acc[1][0] += a1 * b0; acc[1][1] += a1 * b1;
        }
        __syncthreads();
    }
#pragma unroll
    for (int i = 0; i < 2; i++)
#pragma unroll
        for (int j = 0; j < 2; j++)
            g_Wh[OFF_QKV + (col0 + cg * 2 + j) * 192 + row0 + rg * 2 + i] = __float2half(acc[i][j]);
}

// ---------------- fp16 tensor-core GEMM (fp32 or fp16 output) ----------------
__global__ void __launch_bounds__(256) hgemm_kernel(
    const __half* __restrict__ Ah, int woff, const float* __restrict__ bias,
    const float* __restrict__ addvec, float* __restrict__ C, __half* __restrict__ Ch,
    int Ncol)
{
    __shared__ uint32_t sA[128][36];
    __shared__ uint32_t sB[64][36];
    int t = threadIdx.x;
    int wid = t >> 5, lane = t & 31;
    int wm = wid & 3, wn = wid >> 2;
    int g = lane >> 2, la3 = lane & 3;
    int row0 = blockIdx.y * 128, col0 = blockIdx.x * 64;
    const uint32_t* Whu = (const uint32_t*)(g_Wh + woff);
    const uint32_t* Au = (const uint32_t*)Ah;
    uint32_t sAb = (uint32_t)__cvta_generic_to_shared(&sA[0][0]);
    uint32_t sBb = (uint32_t)__cvta_generic_to_shared(&sB[0][0]);
    float acc[2][4][4] = {};
    for (int kp = 0; kp < 3; kp++) {
        int k0 = kp * 64;
        for (int u = t; u < 4096; u += 256) {
            int r = u >> 5, cu = u & 31;
            uint32_t v = Au[(long)(row0 + r) * 96 + (k0 >> 1) + cu];
            if (addvec) {
                float2 f = __half22float2(*(__half2*)&v);
                f.x += addvec[k0 + 2 * cu];
                f.y += addvec[k0 + 2 * cu + 1];
                v = pack_h2(f.x, f.y);
            }
            sA[r][cu] = v;
        }
        for (int u = t; u < 2048; u += 256) {
            int r = u >> 5, cu = u & 31;
            sB[r][cu] = Whu[(col0 + r) * 96 + (k0 >> 1) + cu];
        }
        __syncthreads();
#pragma unroll
        for (int ks = 0; ks < 4; ks++) {
            uint32_t afr[2][4], bfr[2][4];
#pragma unroll
            for (int mt = 0; mt < 2; mt++) {
                uint32_t addr = sAb + 4 * ((32 * wm + 16 * mt + (lane & 15)) * 36
                                           + ks * 8 + (lane >> 4) * 4);
                ldm_x4(afr[mt], addr);
            }
#pragma unroll
            for (int p = 0; p < 2; p++) {
                uint32_t addr = sBb + 4 * ((32 * wn + 16 * p + (lane >> 4) * 8 + (lane & 7)) * 36
                                           + ks * 8 + ((lane >> 3) & 1) * 4);
                ldm_x4(bfr[p], addr);
            }
#pragma unroll
            for (int nt = 0; nt < 4; nt++) {
                int p = nt >> 1, i0 = (nt & 1) * 2;
                mma_f16(acc[0][nt], afr[0], bfr[p][i0], bfr[p][i0 + 1]);
                mma_f16(acc[1][nt], afr[1], bfr[p][i0], bfr[p][i0 + 1]);
            }
        }
        __syncthreads();
    }
#pragma unroll
    for (int mt = 0; mt < 2; mt++) {
#pragma unroll
        for (int nt = 0; nt < 4; nt++) {
            int col = col0 + 32 * wn + 8 * nt + 2 * la3;
            float b0v = bias ? bias[col] : 0.f;
            float b1v = bias ? bias[col + 1] : 0.f;
            int r = row0 + 32 * wm + 16 * mt + g;
            float o00 = acc[mt][nt][0] + b0v, o01 = acc[mt][nt][1] + b1v;
            float o10 = acc[mt][nt][2] + b0v, o11 = acc[mt][nt][3] + b1v;
            if (Ch) {
                *(uint32_t*)&Ch[(long)r * Ncol + col] = pack_h2(o00, o01);
                *(uint32_t*)&Ch[(long)(r + 8) * Ncol + col] = pack_h2(o10, o11);
            } else {
                *(float2*)&C[(long)r * Ncol + col] = make_float2(o00, o01);
                *(float2*)&C[(long)(r + 8) * Ncol + col] = make_float2(o10, o11);
            }
        }
    }
}

// ---------------- A = knnxyz @ pos_W1 + pos_b1 via tf32 mma (K=48) ----------------
__global__ void __launch_bounds__(256) agemm_kernel(const float* __restrict__ pos_b1) {
    __shared__ uint32_t sA[128 * 50];
    __shared__ uint32_t sB[48 * 72];
    int t = threadIdx.x;
    int wid = t >> 5, lane = t & 31;
    int wm = wid & 3, wn = wid >> 2;
    int g = lane >> 2, la3 = lane & 3;
    int row0 = blockIdx.y * 128, col0 = blockIdx.x * 64;
    int m_blk = col0 / 192, cbase = col0 - m_blk * 192;

    for (int u = t; u < 128 * 48; u += 256) {
        int r = u / 48, k = u % 48;
        sA[r * 50 + k] = f2tf32(g_knnxyz[(long)(row0 + r) * 48 + k]);
    }
    for (int u = t; u < 48 * 64; u += 256) {
        int k = u >> 6, n = u & 63;
        sB[k * 72 + n] = g_W1t[k * 576 + col0 + n];
    }
    __syncthreads();

    float acc[2][4][4] = {};
#pragma unroll
    for (int ks = 0; ks < 6; ks++) {
        int ca = ks * 8 + la3;
        uint32_t afr[2][4];
#pragma unroll
        for (int mt = 0; mt < 2; mt++) {
            int r = 32 * wm + 16 * mt + g;
            afr[mt][0] = sA[r * 50 + ca];
            afr[mt][1] = sA[(r + 8) * 50 + ca];
            afr[mt][2] = sA[r * 50 + ca + 4];
            afr[mt][3] = sA[(r + 8) * 50 + ca + 4];
        }
#pragma unroll
        for (int nt = 0; nt < 4; nt++) {
            int nc = 32 * wn + 8 * nt + g;
            uint32_t b0 = sB[ca * 72 + nc];
            uint32_t b1 = sB[(ca + 4) * 72 + nc];
            mma_tf32(acc[0][nt], afr[0], b0, b1);
            mma_tf32(acc[1][nt], afr[1], b0, b1);
        }
    }
#pragma unroll
    for (int mt = 0; mt < 2; mt++) {
#pragma unroll
        for (int nt = 0; nt < 4; nt++) {
            int colL = 32 * wn + 8 * nt + 2 * la3;
            float b0v = pos_b1[col0 + colL], b1v = pos_b1[col0 + colL + 1];
            int r = row0 + 32 * wm + 16 * mt + g;
            *(float2*)&g_A[((long)m_blk * NPTS + r) * DIM + cbase + colL] =
                make_float2(acc[mt][nt][0] + b0v, acc[mt][nt][1] + b1v);
            *(float2*)&g_A[((long)m_blk * NPTS + r + 8) * DIM + cbase + colL] =
                make_float2(acc[mt][nt][2] + b0v, acc[mt][nt][3] + b1v);
        }
    }
}

// ---------------- per-node stage 1 ----------------
__global__ void __launch_bounds__(192) node1_kernel(
    const float* __restrict__ p, const float* __restrict__ x, const int* __restrict__ knn,
    const float* __restrict__ prop_W, const float* __restrict__ prop_b,
    const float* __restrict__ gA_W, const float* __restrict__ gA_b,
    const float* __restrict__ gB_W, const float* __restrict__ gB_b,
    const float* __restrict__ kn, const float* __restrict__ de_W1,
    const float* __restrict__ de_b1, const float* __restrict__ de_W2,
    const float* __restrict__ de_b2)
{
    int n = blockIdx.x;
    int c = threadIdx.x;
    __shared__ float s_p[3];
    __shared__ int   s_idx[NS];
    __shared__ float s_xyz[NS * 3];
    __shared__ float s_pr[NS * 3];
    __shared__ float s_dist[NS];
    __shared__ float s_rep[9];
    __shared__ float s_maxd;
    __shared__ float s_kd[KSP];
    __shared__ float s_g[KSP * DQ];
    __shared__ float s_sc[KSP];
    __shared__ float s_w[DQ];

    if (c < 3) s_p[c] = p[n * 3 + c];
    if (c < NS) s_idx[c] = knn[n * NS + c];
    __syncthreads();

    if (c < NS) {
        int id = s_idx[c];
        float ax = p[id * 3 + 0], ay = p[id * 3 + 1], az = p[id * 3 + 2];
        s_xyz[c * 3 + 0] = ax; s_xyz[c * 3 + 1] = ay; s_xyz[c * 3 + 2] = az;
        float rx = ax - s_p[0], ry = ay - s_p[1], rz = az - s_p[2];
        s_pr[c * 3 + 0] = rx; s_pr[c * 3 + 1] = ry; s_pr[c * 3 + 2] = rz;
        s_dist[c] = sqrtf(rx * rx + ry * ry + rz * rz + 1e-12f);
    }
    if (c >= 32 && c < 32 + KSP) {
        int s = c - 32;
        float dx = s_p[0] - kn[s * 3 + 0];
        float dy = s_p[1] - kn[s * 3 + 1];
        float dz = s_p[2] - kn[s * 3 + 2];
        s_kd[s] = sqrtf(dx * dx + dy * dy + dz * dz + 1e-12f);
    }
    __syncthreads();

    if (c == 0) {
        float mx = 0, my = 0, mz = 0, qx = 0, qy = 0, qz = 0, md = 0, sd = 0;
        for (int j = 0; j < NS; j++) {
            mx += s_pr[j * 3]; my += s_pr[j * 3 + 1]; mz += s_pr[j * 3 + 2];
            qx += s_xyz[j * 3]; qy += s_xyz[j * 3 + 1]; qz += s_xyz[j * 3 + 2];
            md = fmaxf(md, s_dist[j]); sd += s_dist[j];
        }
        const float inv = 1.f / NS;
        s_rep[0] = mx * inv; s_rep[1] = my * inv; s_rep[2] = mz * inv;
        s_rep[3] = qx * inv; s_rep[4] = qy * inv; s_rep[5] = qz * inv;
        s_rep[6] = s_p[0]; s_rep[7] = s_p[1]; s_rep[8] = s_p[2];
        s_maxd = md;
        g_distsum[n] = sd; g_distmax[n] = md;
        g_m3[n * 3 + 0] = qx; g_m3[n * 3 + 1] = qy; g_m3[n * 3 + 2] = qz;
    }
    if (c < NS * 3) g_knnxyz[n * 48 + c] = s_xyz[c];
    for (int idx = c; idx < KSP * DQ; idx += 192) {
        int s = idx / DQ, k = idx % DQ;
        s_g[idx] = fmaxf(s_kd[s] * de_W1[k] + de_b1[k], 0.f);
    }
    __syncthreads();

    if (c < KSP) {
        float l = g_kpconst;
        for (int k = 0; k < DQ; k++) l += s_g[c * DQ + k] * g_kpwproj[k];
        s_sc[c] = l;
    }
    __syncthreads();
    if (c == 0) {
        float mx = -1e30f;
        for (int s = 0; s < KSP; s++) mx = fmaxf(mx, s_sc[s]);
        float se = 0.f;
        for (int s = 0; s < KSP; s++) { float e = expf(s_sc[s] - mx); s_sc[s] = e; se += e; }
        float inv = 1.f / se;
        for (int s = 0; s < KSP; s++) s_sc[s] *= inv;
    }
    __syncthreads();
    if (c < DQ) {
        float w = 0.f;
        for (int s = 0; s < KSP; s++) w += s_sc[s] * s_g[s * DQ + c];
        s_w[c] = w;
    }
    __syncthreads();

    float dist_feat = de_b2[c];
#pragma unroll
    for (int k = 0; k < DQ; k++) dist_feat += s_w[k] * de_W2[k * DIM + c];

    float geo = gA_b[c] + gB_b[c] + s_maxd * gB_W[c];
#pragma unroll
    for (int i = 0; i < 9; i++) geo += s_rep[i] * gA_W[i * DIM + c];

    float w0 = prop_W[192 * DIM + c], w1 = prop_W[193 * DIM + c], w2 = prop_W[194 * DIM + c];
    float pb = prop_b[c];
    float msg = 0.f;
#pragma unroll
    for (int s = 0; s < NS; s++) {
        float v = g_xpw[(long)s_idx[s] * DIM + c]
                + s_pr[s * 3] * w0 + s_pr[s * 3 + 1] * w1 + s_pr[s * 3 + 2] * w2 + pb;
        msg += fmaxf(v, 0.f);
    }
    msg *= (1.f / NS);
    g_prefh[(long)n * DIM + c] = __float2half(x[(long)n * DIM + c] + msg + geo + dist_feat);
}

// ---------------- global reductions ----------------
__global__ void __launch_bounds__(256) reduce_kernel() {
    int tid = blockIdx.x * blockDim.x + threadIdx.x;
    int stride = gridDim.x * blockDim.x;
    double lsum = 0, l0 = 0, l1 = 0, l2 = 0;
    float lmax = 0.f;
    for (int n = tid; n < NPTS; n += stride) {
        lsum += (double)g_distsum[n];
        lmax = fmaxf(lmax, g_distmax[n]);
        l0 += (double)g_m3[n * 3 + 0];
        l1 += (double)g_m3[n * 3 + 1];
        l2 += (double)g_m3[n * 3 + 2];
    }
    double m0 = 0, m1 = 0, m2 = 0, m3v = 0, m4 = 0, m5 = 0;
    for (int idx = tid; idx < NPTS * NS; idx += stride) {
        float xx = g_knnxyz[idx * 3 + 0];
        float yy = g_knnxyz[idx * 3 + 1];
        float zz = g_knnxyz[idx * 3 + 2];
        m0 += (double)xx * xx; m1 += (double)xx * yy; m2 += (double)xx * zz;
        m3v += (double)yy * yy; m4 += (double)yy * zz; m5 += (double)zz * zz;
    }
    lsum = dwarpsum(lsum); l0 = dwarpsum(l0); l1 = dwarpsum(l1); l2 = dwarpsum(l2);
    m0 = dwarpsum(m0); m1 = dwarpsum(m1); m2 = dwarpsum(m2);
    m3v = dwarpsum(m3v); m4 = dwarpsum(m4); m5 = dwarpsum(m5);
#pragma unroll
    for (int o = 16; o > 0; o >>= 1) lmax = fmaxf(lmax, __shfl_xor_sync(0xffffffffu, lmax, o));
    if ((threadIdx.x & 31) == 0) {
        atomicAdd(&g_sumdist, lsum);
        atomicAdd(&g_Sm3[0], l0); atomicAdd(&g_Sm3[1], l1); atomicAdd(&g_Sm3[2], l2);
        atomicAdd(&g_SM33[0], m0); atomicAdd(&g_SM33[1], m1); atomicAdd(&g_SM33[2], m2);
        atomicAdd(&g_SM33[3], m3v); atomicAdd(&g_SM33[4], m4); atomicAdd(&g_SM33[5], m5);
        atomicMax(&g_maxbits, __float_as_int(lmax));
    }
}

// ---------------- BN per-channel statistics ----------------
#define BNCHUNK 64
__global__ void __launch_bounds__(192) bnstats_kernel() {
    int m = blockIdx.y;
    int n0 = blockIdx.x * BNCHUNK;
    int c = threadIdx.x;
    float sa = 0, sa2 = 0, sx = 0, sy = 0, sz = 0;
    const float* Abase = g_A + (long)m * NPTS * DIM;
    for (int n = n0; n < n0 + BNCHUNK; n++) {
        float a = Abase[(long)n * DIM + c];
        float mx = g_m3[n * 3 + 0], my = g_m3[n * 3 + 1], mz = g_m3[n * 3 + 2];
        sa += a;
        sa2 += a * a;
        sx += a * mx; sy += a * my; sz += a * mz;
    }
    double* d = g_ch + ((long)m * DIM + c) * 5;
    atomicAdd(d + 0, (double)sa); atomicAdd(d + 1, (double)sa2);
    atomicAdd(d + 2, (double)sx); atomicAdd(d + 3, (double)sy); atomicAdd(d + 4, (double)sz);
}

// ---------------- finalize ----------------
__global__ void __launch_bounds__(192) finalize_kernel(
    const float* __restrict__ pos_W1, const float* __restrict__ pos_gamma,
    const float* __restrict__ pos_beta, const float* __restrict__ gC_W,
    const float* __restrict__ gC_b)
{
    int c = threadIdx.x;
    float Sv[3][3];
#pragma unroll
    for (int m = 0; m < 3; m++)
#pragma unroll
        for (int k = 0; k < 3; k++) {
            float s = 0.f;
            for (int j = 0; j < NS; j++) s += pos_W1[(long)m * 48 * DIM + (3 * j + k) * DIM + c];
            Sv[m][k] = s;
            g_S[(m * 3 + k) * DIM + c] = s;
        }
    const double T = (double)NPTS * NS;
    double Q0 = g_SM33[0], Q1 = g_SM33[1], Q2 = g_SM33[2], Q3 = g_SM33[3], Q4 = g_SM33[4], Q5 = g_SM33[5];
    double P0 = g_Sm3[0], P1 = g_Sm3[1], P2 = g_Sm3[2];
#pragma unroll
    for (int m = 0; m < 3; m++) {
        const double* d = g_ch + ((long)m * DIM + c) * 5;
        double SA = d[0], SA2 = d[1], SMx = d[2], SMy = d[3], SMz = d[4];
        double Sx = Sv[m][0], Sy = Sv[m][1], Sz = Sv[m][2];
        double mean = (16.0 * SA - (Sx * P0 + Sy * P1 + Sz * P2)) / T;
        double sq = 16.0 * SA2 - 2.0 * (Sx * SMx + Sy * SMy + Sz * SMz)
                  + Sx * Sx * Q0 + Sy * Sy * Q3 + Sz * Sz * Q5
                  + 2.0 * (Sx * Sy * Q1 + Sx * Sz * Q2 + Sy * Sz * Q4);
        double var = sq / T - mean * mean;
        float sc = pos_gamma[m * DIM + c] * rsqrtf((float)(var + 1e-5));
        g_bnscale[m * DIM + c] = sc;
        g_bnshift[m * DIM + c] = pos_beta[m * DIM + c] - (float)mean * sc;
    }
    float maxd = __int_as_float(g_maxbits);
    float vol = (float)(g_sumdist / T) / (maxd + 1e-8f);
    g_volvec[c] = vol * gC_W[c] + gC_b[c];
}

// ---------------- fused attention: U-factorized scores + proven pv path ----------------
#define SH_OFF    0          // 2 x 128 x 100 u32 = 102400
#define SU_OFF    102400     // 36864
#define SQ_OFF    139264     // 6144
#define SK_OFF    145408     // 6144
#define SQH_OFF   151552     // 6400
#define SKH_OFF   157952     // 6400
#define SB2_OFF   164352     // 2304
#define SSC_OFF   166656     // 3072
#define SWT_OFF   169728     // 3072
#define SXYZ_OFF  172800     // 1536
#define SIDX_OFF  174336     // 512
#define SAH_OFF   174848     // 18432
#define SSH_OFF   193280     // 6912
#define ATT_SMEM  200192

__global__ void __launch_bounds__(512, 1) attn_mma_kernel(
    const int* __restrict__ knn, const float* __restrict__ pos_b2)
{
    extern __shared__ char smem[];
    const int t = threadIdx.x;
    const int wid = t >> 5, lane = t & 31;
    const int wm = wid & 3, wn = wid >> 2;
    const int g = lane >> 2, la3 = lane & 3;
    const int nb = blockIdx.x * 8;

    uint32_t* s_h  = (uint32_t*)(smem + SH_OFF);
    uint32_t* s_u  = (uint32_t*)(smem + SU_OFF);
    float* s_q   = (float*)(smem + SQ_OFF);
    float* s_k0  = (float*)(smem + SK_OFF);
    uint32_t* s_qh = (uint32_t*)(smem + SQH_OFF);
    uint32_t* s_kh = (uint32_t*)(smem + SKH_OFF);
    float* s_b2  = (float*)(smem + SB2_OFF);
    float* s_sc  = (float*)(smem + SSC_OFF);
    float* s_w   = (float*)(smem + SWT_OFF);
    float* s_xyz = (float*)(smem + SXYZ_OFF);
    int*   s_idx = (int*)(smem + SIDX_OFF);
    float* s_ahat = (float*)(smem + SAH_OFF);
    float* s_Sh   = (float*)(smem + SSH_OFF);
    const uint32_t shb  = (uint32_t)__cvta_generic_to_shared(smem + SH_OFF);
    const uint32_t sqhb = (uint32_t)__cvta_generic_to_shared(smem + SQH_OFF);
    const uint32_t skhb = (uint32_t)__cvta_generic_to_shared(smem + SKH_OFF);

    const int grow = t >> 2;
    const int gn2 = grow >> 4, gj2 = grow & 15;

    // ---- phase A: stage shared inputs ----
    for (int u = t; u < 128; u += 512) s_idx[u] = knn[(nb + (u >> 4)) * NS + (u & 15)];
    for (int u = t; u < 8 * 48; u += 512) s_xyz[u] = g_knnxyz[(long)nb * 48 + u];
    for (int u = t; u < 3 * DIM; u += 512) s_b2[u] = pos_b2[u];
    for (int u = t; u < 8 * (DIM / 2); u += 512) {
        int n = u / (DIM / 2), cp = u % (DIM / 2);
        long r0h = (long)knn[(nb + n) * NS] * 288;   // row base in uint32 units (576 halves)
        float2 qv = up_h2(((const uint32_t*)g_qkvh)[r0h + cp]);
        float2 kv = up_h2(((const uint32_t*)g_qkvh)[r0h + 96 + cp]);
        *(float2*)&s_q[n * DIM + 2 * cp] = qv;
        *(float2*)&s_k0[n * DIM + 2 * cp] = kv;
    }
    for (int u = t; u < 3 * 8 * DIM; u += 512) {
        int m = u / (8 * DIM);
        int rem = u - m * 8 * DIM;
        int node = rem / DIM, cg = rem % DIM;
        float a = g_A[((long)m * NPTS + nb + node) * DIM + cg];
        s_ahat[u] = a * g_bnscale[m * DIM + cg] + g_bnshift[m * DIM + cg];
    }
    for (int u = t; u < 3 * 3 * DIM; u += 512) {
        int m = u / (3 * DIM);
        int rem = u - m * 3 * DIM;
        s_Sh[u] = g_S[(m * 3 + rem / DIM) * DIM + (rem % DIM)] * g_bnscale[m * DIM + rem % DIM];
    }
    __syncthreads();

    // ---- phase B: base scores + gen h (mats 0,1) + fp16 q0/k0 staging ----
    for (int task = t; task < 768; task += 512) {
        int n = task / 96, h = (task / 16) % 6, j = task & 15;
        const float4* qv = (const float4*)(s_q + n * DIM + 32 * h);
        const float4* kv0 = (const float4*)(s_k0 + n * DIM + 32 * h);
        const float4* b0 = (const float4*)(s_b2 + 32 * h);
        const float4* b1 = (const float4*)(s_b2 + DIM + 32 * h);
        const uint4* kj = (const uint4*)((const uint32_t*)g_qkvh
                            + (long)s_idx[n * 16 + j] * 288 + 96 + 16 * h);
        float dot = 0.f;
#pragma unroll
        for (int u = 0; u < 4; u++) {
            uint4 kk = kj[u];
            float2 k0p = up_h2(kk.x), k1p = up_h2(kk.y), k2p = up_h2(kk.z), k3p = up_h2(kk.w);
            float4 q4a = qv[2 * u], q4b = qv[2 * u + 1];
            float4 b0a = b0[2 * u], b0b = b0[2 * u + 1];
            float4 b1a = b1[2 * u], b1b = b1[2 * u + 1];
            float4 kka = kv0[2 * u], kkb = kv0[2 * u + 1];
            dot += q4a.x * (k0p.x + b0a.x) + q4a.y * (k0p.y + b0a.y)
                 + q4a.z * (k1p.x + b0a.z) + q4a.w * (k1p.y + b0a.w)
                 + q4b.x * (k2p.x + b0b.x) + q4b.y * (k2p.y + b0b.y)
                 + q4b.z * (k3p.x + b0b.z) + q4b.w * (k3p.y + b0b.w);
            dot += kka.x * b1a.x + kka.y * b1a.y + kka.z * b1a.z + kka.w * b1a.w
                 + kkb.x * b1b.x + kkb.y * b1b.y + kkb.z * b1b.z + kkb.w * b1b.w;
        }
        s_sc[(n * 6 + h) * 16 + j] = dot;
    }
    {
        float xx = s_xyz[gn2 * 48 + gj2 * 3 + 0];
        float yy = s_xyz[gn2 * 48 + gj2 * 3 + 1];
        float zz = s_xyz[gn2 * 48 + gj2 * 3 + 2];
#pragma unroll
        for (int m = 0; m < 2; m++) {
            const float* ah = s_ahat + m * 8 * DIM + gn2 * DIM;
            const float* Sh = s_Sh + m * 3 * DIM;
            uint32_t* hdst = s_h + m * 12800 + grow * 100;
#pragma unroll
            for (int i = 0; i < 24; i++) {
                int cu = (t & 3) + 4 * i;
                int cg = 2 * cu;
                float2 a2 = *(const float2*)&ah[cg];
                float2 S0 = *(const float2*)&Sh[cg];
                float2 S1 = *(const float2*)&Sh[DIM + cg];
                float2 S2 = *(const float2*)&Sh[2 * DIM + cg];
                float h0 = a2.x - (xx * S0.x + yy * S1.x + zz * S2.x);
                float h1 = a2.y - (xx * S0.y + yy * S1.y + zz * S2.y);
                hdst[cu] = pack_h2(fmaxf(h0, 0.f), fmaxf(h1, 0.f));
            }
        }
    }
    for (int u = t; u < 1600; u += 512) {
        int row = u / 100, cu = u % 100;
        uint32_t vq = 0, vk = 0;
        if (row < 8 && cu < 96) {
            vq = pack_h2(s_q[row * DIM + 2 * cu], s_q[row * DIM + 2 * cu + 1]);
            vk = pack_h2(s_k0[row * DIM + 2 * cu], s_k0[row * DIM + 2 * cu + 1]);
        }
        s_qh[u] = vq;
        s_kh[u] = vk;
    }
    __syncthreads();

    // ---- phase C: U-mma (12 warps) ----
    if (wid < 12) {
        int m = wid / 6, hh = wid % 6;
        uint32_t xb = (m == 0) ? sqhb : skhb;
        const uint2* wt = g_W2u + ((m * 6 + hh) * 24) * 64;
#pragma unroll 4
        for (int nt = 0; nt < 24; nt++) {
            float acc[4] = {0.f, 0.f, 0.f, 0.f};
#pragma unroll
            for (int ks = 0; ks < 2; ks++) {
                uint32_t afr[4];
                ldm_x4(afr, xb + 4 * ((lane & 15) * 100 + 16 * hh + ks * 8 + (lane >> 4) * 4));
                uint2 bb = wt[(nt * 2 + ks) * 32 + lane];
                mma_f16(acc, afr, bb.x, bb.y);
            }
            s_u[((m * 8 + g) * 6 + hh) * 96 + 4 * nt + la3] = pack_h2(acc[0], acc[1]);
        }
    }
    __syncthreads();

    // ---- phase C2: score-mma (16 warps) ----
    {
        int m = wid >> 3, n = wid & 7;
        float acc[4] = {0.f, 0.f, 0.f, 0.f};
        const uint32_t* ub = s_u + (m * 8 + n) * 6 * 96;
#pragma unroll
        for (int ks = 0; ks < 12; ks++) {
            uint32_t afr[4];
            ldm_x4(afr, shb + 4 * (m * 12800 + (n * 16 + (lane & 15)) * 100 + ks * 8 + (lane >> 4) * 4));
            uint32_t b0 = 0, b1 = 0;
            if (g < 6) {
                b0 = ub[g * 96 + ks * 8 + la3];
                b1 = ub[g * 96 + ks * 8 + la3 + 4];
            }
            mma_f16(acc, afr, b0, b1);
        }
        int h0 = 2 * la3;
        if (h0 < 6) {
            atomicAdd(&s_sc[(n * 6 + h0) * 16 + g], acc[0]);
            atomicAdd(&s_sc[(n * 6 + h0) * 16 + g + 8], acc[2]);
        }
        if (h0 + 1 < 6) {
            atomicAdd(&s_sc[(n * 6 + h0 + 1) * 16 + g], acc[1]);
            atomicAdd(&s_sc[(n * 6 + h0 + 1) * 16 + g + 8], acc[3]);
        }
    }
    __syncthreads();

    // ---- phase D: softmax + gen h mat 2 (into buffer 0) ----
    {
        float xx = s_xyz[gn2 * 48 + gj2 * 3 + 0];
        float yy = s_xyz[gn2 * 48 + gj2 * 3 + 1];
        float zz = s_xyz[gn2 * 48 + gj2 * 3 + 2];
        const float* ah = s_ahat + 2 * 8 * DIM + gn2 * DIM;
        const float* Sh = s_Sh + 2 * 3 * DIM;
        uint32_t* hdst = s_h + grow * 100;
#pragma unroll
        for (int i = 0; i < 24; i++) {
            int cu = (t & 3) + 4 * i;
            int cg = 2 * cu;
            float2 a2 = *(const float2*)&ah[cg];
            float2 S0 = *(const float2*)&Sh[cg];
            float2 S1 = *(const float2*)&Sh[DIM + cg];
            float2 S2 = *(const float2*)&Sh[2 * DIM + cg];
            float h0 = a2.x - (xx * S0.x + yy * S1.x + zz * S2.x);
            float h1 = a2.y - (xx * S0.y + yy * S1.y + zz * S2.y);
            hdst[cu] = pack_h2(fmaxf(h0, 0.f), fmaxf(h1, 0.f));
        }
    }
    if (t < 48) {
        const float scale = 0.17677669529663687f;  // 32^-0.5
        float* sc = s_sc + t * 16;
        float mx = -1e30f;
#pragma unroll
        for (int j = 0; j < 16; j++) mx = fmaxf(mx, sc[j]);
        float se = 0.f;
        float ev[16];
#pragma unroll
        for (int j = 0; j < 16; j++) { ev[j] = expf((sc[j] - mx) * scale); se += ev[j]; }
        float inv = 1.f / se;
#pragma unroll
        for (int j = 0; j < 16; j++) s_w[t * 16 + j] = ev[j] * inv;
    }
    __syncthreads();

    // ---- phase E: pv-mma (16 warps) + output epilogue ----
    {
        float acc[2][6][4];
#pragma unroll
        for (int a1 = 0; a1 < 2; a1++)
#pragma unroll
            for (int a2 = 0; a2 < 6; a2++)
#pragma unroll
                for (int a3 = 0; a3 < 4; a3++) acc[a1][a2][a3] = 0.f;

#pragma unroll
        for (int ks = 0; ks < 12; ks++) {
            const uint4* bq = (const uint4*)g_W2f + (((2 * 4 + wn) * 12 + ks) * 3) * 32;
            uint4 u0 = bq[lane];
            uint4 u1 = bq[32 + lane];
            uint4 u2 = bq[64 + lane];
            uint32_t afr[2][4];
#pragma unroll
            for (int mt = 0; mt < 2; mt++) {
                uint32_t addr = shb + 4 * ((32 * wm + 16 * mt + (lane & 15)) * 100
                                           + ks * 8 + (lane >> 4) * 4);
                ldm_x4(afr[mt], addr);
            }
            mma_f16(acc[0][0], afr[0], u0.x, u0.y);
            mma_f16(acc[1][0], afr[1], u0.x, u0.y);
            mma_f16(acc[0][1], afr[0], u0.z, u0.w);
            mma_f16(acc[1][1], afr[1], u0.z, u0.w);
            mma_f16(acc[0][2], afr[0], u1.x, u1.y);
            mma_f16(acc[1][2], afr[1], u1.x, u1.y);
            mma_f16(acc[0][3], afr[0], u1.z, u1.w);
            mma_f16(acc[1][3], afr[1], u1.z, u1.w);
            mma_f16(acc[0][4], afr[0], u2.x, u2.y);
            mma_f16(acc[1][4], afr[1], u2.x, u2.y);
            mma_f16(acc[0][5], afr[0], u2.z, u2.w);
            mma_f16(acc[1][5], afr[1], u2.z, u2.w);
        }

#pragma unroll
        for (int mt = 0; mt < 2; mt++) {
            int node = 2 * wm + mt;
            int j0 = g;
            long v0b = (long)s_idx[node * 16 + j0] * 288 + 192;   // uint32 units
            long v1b = (long)s_idx[node * 16 + j0 + 8] * 288 + 192;
#pragma unroll
            for (int nt = 0; nt < 6; nt++) {
                int c0 = 48 * wn + 8 * nt + 2 * la3;
                int h = c0 >> 5;
                float w0 = s_w[(node * 6 + h) * 16 + j0];
                float w1 = s_w[(node * 6 + h) * 16 + j0 + 8];
                float b20 = s_b2[2 * DIM + c0], b21 = s_b2[2 * DIM + c0 + 1];
                float2 v0p = up_h2(((const uint32_t*)g_qkvh)[v0b + (c0 >> 1)]);
                float2 v1p = up_h2(((const uint32_t*)g_qkvh)[v1b + (c0 >> 1)]);
                float o0 = w0 * (acc[mt][nt][0] + v0p.x + b20)
                         + w1 * (acc[mt][nt][2] + v1p.x + b20);
                float o1 = w0 * (acc[mt][nt][1] + v0p.y + b21)
                         + w1 * (acc[mt][nt][3] + v1p.y + b21);
#pragma unroll
                for (int o = 4; o < 32; o <<= 1) {
                    o0 += __shfl_xor_sync(0xffffffffu, o0, o);
                    o1 += __shfl_xor_sync(0xffffffffu, o1, o);
                }
                if (g == 0) {
                    *(uint32_t*)(g_atth + (long)(nb + node) * DIM + c0) = pack_h2(o0, o1);
                }
            }
        }
    }
}

// ---------------- host launcher ----------------
extern "C" void kernel_launch(void* const* d_in, const int* in_sizes, int n_in,
                              void* d_out, int out_size)
{
    const float* p      = (const float*)d_in[0];
    const float* x      = (const float*)d_in[1];
    const int*   knn    = (const int*)d_in[2];
    const float* W_qkv  = (const float*)d_in[3];
    const float* W_proj = (const float*)d_in[4];
    const float* b_proj = (const float*)d_in[5];
    const float* prop_W = (const float*)d_in[6];
    const float* prop_b = (const float*)d_in[7];
    const float* gA_W   = (const float*)d_in[8];
    const float* gA_b   = (const float*)d_in[9];
    const float* gB_W   = (const float*)d_in[10];
    const float* gB_b   = (const float*)d_in[11];
    const float* gC_W   = (const float*)d_in[12];
    const float* gC_b   = (const float*)d_in[13];
    const float* pos_W1 = (const float*)d_in[14];
    const float* pos_b1 = (const float*)d_in[15];
    const float* pos_gamma = (const float*)d_in[16];
    const float* pos_beta  = (const float*)d_in[17];
    const float* pos_W2 = (const float*)d_in[18];
    const float* pos_b2 = (const float*)d_in[19];
    const float* kn     = (const float*)d_in[20];
    const float* de_W1  = (const float*)d_in[21];
    const float* de_b1  = (const float*)d_in[22];
    const float* de_W2  = (const float*)d_in[23];
    const float* de_b2  = (const float*)d_in[24];
    const float* kp_W   = (const float*)d_in[25];
    const float* kp_b   = (const float*)d_in[26];
    const float* fus_W  = (const float*)d_in[27];
    const float* fus_b  = (const float*)d_in[28];
    float* out = (float*)d_out;

    float *xpw, *volvec, *bfq;
    __half *xh, *prefh, *atth, *qkvh;
    cudaGetSymbolAddress((void**)&xpw, g_xpw);
    cudaGetSymbolAddress((void**)&volvec, g_volvec);
    cudaGetSymbolAddress((void**)&bfq, g_bfq);
    cudaGetSymbolAddress((void**)&xh, g_xh);
    cudaGetSymbolAddress((void**)&prefh, g_prefh);
    cudaGetSymbolAddress((void**)&atth, g_atth);
    cudaGetSymbolAddress((void**)&qkvh, g_qkvh);

    cudaFuncSetAttribute(attn_mma_kernel, cudaFuncAttributeMaxDynamicSharedMemorySize, ATT_SMEM);

    prep_kernel<<<512, 256>>>(prop_W, W_proj, pos_W1, x);
    small_kernel<<<4, 192>>>(de_W2, de_b2, kp_W, kp_b, fus_b, W_qkv);
    w2f_kernel<<<216, 256>>>(pos_W2);
    w2u_kernel<<<144, 256>>>(pos_W2);
    wfq_kernel<<<dim3(18, 6), 256>>>(fus_W, W_qkv);
    hgemm_kernel<<<dim3(3, 128), 256>>>(xh, OFF_PROP, nullptr, nullptr, xpw, nullptr, 192);
    node1_kernel<<<NPTS, 192>>>(p, x, knn, prop_W, prop_b, gA_W, gA_b, gB_W, gB_b,
                                kn, de_W1, de_b1, de_W2, de_b2);
    agemm_kernel<<<dim3(9, 128), 256>>>(pos_b1);
    reduce_kernel<<<128, 256>>>();
    bnstats_kernel<<<dim3(NPTS / BNCHUNK, 3), 192>>>();
    finalize_kernel<<<1, 192>>>(pos_W1, pos_gamma, pos_beta, gC_W, gC_b);
    hgemm_kernel<<<dim3(9, 128), 256>>>(prefh, OFF_QKV, bfq, volvec, nullptr, qkvh, 576);
    attn_mma_kernel<<<NPTS / 8, 512, ATT_SMEM>>>(knn, pos_b2);
    hgemm_kernel<<<dim3(3, 128), 256>>>(atth, OFF_PROJ, b_proj, nullptr, out, nullptr, 192);
}

// round 16
// speedup vs baseline: 1.1420x; 1.0280x over previous
#include <cuda_runtime.h>
#include <cuda_fp16.h>
#include <math.h>
#include <stdint.h>

#define NPTS 16384
#define DIM  192
#define NS   16
#define NH   6
#define HD   32
#define KSP  16
#define DQ   48

// ---------------- scratch (device globals; no allocs allowed) ----------------
__device__ __half g_xpwh[NPTS * DIM];      // x @ prop_W[:192] as half
__device__ __half g_qkvh[NPTS * 576];      // qkv as half
__device__ __half g_Ah[3L * NPTS * DIM];   // A as half
__device__ float g_knnxyz[NPTS * 48];
__device__ float g_m3[NPTS * 3];
__device__ float g_distsum[NPTS];
__device__ float g_distmax[NPTS];
__device__ double g_ch[3 * DIM * 5];
__device__ double g_Sm3[3];
__device__ double g_SM33[6];
__device__ double g_sumdist;
__device__ int    g_maxbits;
__device__ float g_S[9 * DIM];
__device__ float g_bnscale[3 * DIM];
__device__ float g_bnshift[3 * DIM];
__device__ float g_volvec[DIM];
__device__ float g_kpwproj[DQ];
__device__ float g_kpconst;
__device__ __half g_Wh[184320];            // dense weights as half, [n][k=192]
__device__ uint32_t g_W1t[48 * 576];       // pos_W1 as tf32 bits
__device__ float g_bfq[576];               // fus_b @ W_qkv
__device__ uint32_t g_W2f[55296];          // pos_W2 fp16 mma fragments (m=2 slice used)
__device__ uint2 g_W2u[18432];             // W2^T fragments for U-mma
__device__ __half g_xh[NPTS * DIM];        // x as half
__device__ __half g_prefh[NPTS * DIM];     // prefus as half
__device__ __half g_atth[NPTS * DIM];      // attn out as half

#define OFF_PROP 0
#define OFF_QKV  36864
#define OFF_PROJ 147456

__device__ __forceinline__ void mma_f16(float* c, const uint32_t* a, uint32_t b0, uint32_t b1) {
    asm volatile("mma.sync.aligned.m16n8k16.row.col.f32.f16.f16.f32 "
        "{%0,%1,%2,%3}, {%4,%5,%6,%7}, {%8,%9}, {%0,%1,%2,%3};"
        : "+f"(c[0]), "+f"(c[1]), "+f"(c[2]), "+f"(c[3])
        : "r"(a[0]), "r"(a[1]), "r"(a[2]), "r"(a[3]), "r"(b0), "r"(b1));
}
__device__ __forceinline__ void mma_tf32(float* c, const uint32_t* a, uint32_t b0, uint32_t b1) {
    asm volatile("mma.sync.aligned.m16n8k8.row.col.f32.tf32.tf32.f32 "
        "{%0,%1,%2,%3}, {%4,%5,%6,%7}, {%8,%9}, {%0,%1,%2,%3};"
        : "+f"(c[0]), "+f"(c[1]), "+f"(c[2]), "+f"(c[3])
        : "r"(a[0]), "r"(a[1]), "r"(a[2]), "r"(a[3]), "r"(b0), "r"(b1));
}
__device__ __forceinline__ void ldm_x4(uint32_t* d, uint32_t a) {
    asm volatile("ldmatrix.sync.aligned.m8n8.x4.shared.b16 {%0,%1,%2,%3}, [%4];"
        : "=r"(d[0]), "=r"(d[1]), "=r"(d[2]), "=r"(d[3]) : "r"(a));
}
__device__ __forceinline__ uint32_t pack_h2(float a, float b) {
    __half2 h = __floats2half2_rn(a, b);
    return *(uint32_t*)&h;
}
__device__ __forceinline__ float2 up_h2(uint32_t v) {
    return __half22float2(*(__half2*)&v);
}
__device__ __forceinline__ uint32_t f2tf32(float f) {
    uint32_t r;
    asm("cvt.rna.tf32.f32 %0, %1;" : "=r"(r) : "f"(f));
    return r;
}
__device__ __forceinline__ double dwarpsum(double v) {
#pragma unroll
    for (int o = 16; o > 0; o >>= 1) v += __shfl_xor_sync(0xffffffffu, v, o);
    return v;
}

// ---------------- merged prep: zeros + weight converts + x->half ----------------
__global__ void __launch_bounds__(256) prep_kernel(
    const float* __restrict__ prop_W, const float* __restrict__ W_proj,
    const float* __restrict__ pos_W1, const float* __restrict__ x)
{
    int gid = blockIdx.x * 256 + threadIdx.x;
    int stride = gridDim.x * 256;
    for (int i = gid; i < 3 * DIM * 5; i += stride) g_ch[i] = 0.0;
    if (gid < 3) g_Sm3[gid] = 0.0;
    if (gid < 6) g_SM33[gid] = 0.0;
    if (gid == 0) { g_sumdist = 0.0; g_maxbits = 0; }
    for (int i = gid; i < 192 * 192; i += stride) {
        int k = i / 192, n = i % 192;
        g_Wh[OFF_PROP + n * 192 + k] = __float2half(prop_W[i]);
        g_Wh[OFF_PROJ + n * 192 + k] = __float2half(W_proj[i]);
    }
    for (int i = gid; i < 48 * 576; i += stride) {
        int k = i / 576, n = i % 576;
        int m = n / 192, c = n % 192;
        g_W1t[i] = f2tf32(pos_W1[((long)m * 48 + k) * 192 + c]);
    }
    for (int i = gid; i < NPTS * DIM / 2; i += stride) {
        float2 v = ((const float2*)x)[i];
        ((uint32_t*)g_xh)[i] = pack_h2(v.x, v.y);
    }
}

// ---------------- merged tiny precompute ----------------
__global__ void __launch_bounds__(192) small_kernel(
    const float* __restrict__ de_W2, const float* __restrict__ de_b2,
    const float* __restrict__ kp_W, const float* __restrict__ kp_b,
    const float* __restrict__ fus_b, const float* __restrict__ W_qkv)
{
    int b = blockIdx.x, t = threadIdx.x;
    if (b == 0) {
        if (t < DQ) {
            float s = 0.f;
            for (int c = 0; c < DIM; c++) s += de_W2[t * DIM + c] * kp_W[c];
            g_kpwproj[t] = s;
        }
        if (t == 63) {
            float s = 0.f;
            for (int c = 0; c < DIM; c++) s += de_b2[c] * kp_W[c];
            g_kpconst = s + kp_b[0];
        }
    } else {
        int n = (b - 1) * 192 + t;
        if (n < 576) {
            float s = 0.f;
            for (int j = 0; j < 192; j++) s += fus_b[j] * W_qkv[j * 576 + n];
            g_bfq[n] = s;
        }
    }
}

// ---------------- pos_W2 -> fragment table (mat 2 pv usage) ----------------
__global__ void __launch_bounds__(256) w2f_kernel(const float* __restrict__ pos_W2) {
    int gid = blockIdx.x * 256 + threadIdx.x;
    if (gid >= 55296) return;
    int e = gid & 3;
    int r = gid >> 2;
    int lane = r & 31; r >>= 5;
    int qq = r % 3; r /= 3;
    int ks = r % 12; r /= 12;
    int wn = r & 3;
    int m = r >> 2;
    int q = qq * 4 + e;
    int nt = q >> 1, ib = q & 1;
    int g = lane >> 2, la3 = lane & 3;
    int nr = 48 * wn + 8 * nt + g;
    int o = ks * 8 + la3 + 4 * ib;
    const float* W2m = pos_W2 + (long)m * DIM * DIM;
    g_W2f[gid] = pack_h2(W2m[(2 * o) * DIM + nr], W2m[(2 * o + 1) * DIM + nr]);
}

// ---------------- W2^T fragments for per-block U-mma (mats 0,1) ----------------
__global__ void __launch_bounds__(256) w2u_kernel(const float* __restrict__ pos_W2) {
    int gid = blockIdx.x * 256 + threadIdx.x;
    if (gid >= 36864) return;
    int e = gid & 1;
    int r = gid >> 1;
    int lane = r & 31; r >>= 5;
    int ks = r & 1; r >>= 1;
    int nt = r % 24; r /= 24;
    int h = r % 6;
    int m = r / 6;                  // 0..1
    int g = lane >> 2, la3 = lane & 3;
    int nr = 8 * nt + g;            // output k index 0..191
    int cl = 16 * ks + 8 * e + 2 * la3;
    int cout = 32 * h + cl;
    const float* W2m = pos_W2 + (long)m * DIM * DIM;
    ((uint32_t*)g_W2u)[((((m * 6 + h) * 24 + nt) * 2 + ks) * 32 + lane) * 2 + e] =
        pack_h2(W2m[nr * DIM + cout], W2m[nr * DIM + cout + 1]);
}

// ---------------- Wfq = fus_W @ W_qkv : 32x32 tiles ----------------
__global__ void __launch_bounds__(256) wfq_kernel(const float* __restrict__ fus_W,
                                                  const float* __restrict__ W_qkv) {
    __shared__ float As[16][33];
    __shared__ float Bs[16][33];
    int t = threadIdx.x;
    int row0 = blockIdx.y * 32;
    int col0 = blockIdx.x * 32;
    int rg = t / 16, cg = t % 16;
    int a_k = t % 16, a_m = t / 16;
    float acc[2][2] = {};
    for (int k0 = 0; k0 < 192; k0 += 16) {
#pragma unroll
        for (int p = 0; p < 2; p++)
            As[a_k][a_m + p * 16] = fus_W[(row0 + a_m + p * 16) * 192 + k0 + a_k];
#pragma unroll
        for (int p = 0; p < 2; p++) {
            int u = t + p * 256;
            int kk = u >> 5, n = u & 31;
            Bs[kk][n] = W_qkv[(k0 + kk) * 576 + col0 + n];
        }
        __syncthreads();
#pragma unroll
        for (int kk = 0; kk < 16; kk++) {
            float a0 = As[kk][rg * 2], a1 = As[kk][rg * 2 + 1];
            float b0 = Bs[kk][cg * 2], b1 = Bs[kk][cg * 2 + 1];
            acc[0][0] += a0 * b0; acc[0][1] += a0 * b1;
            acc[1][0] += a1 * b0; acc[1][1] += a1 * b1;
        }
        __syncthreads();
    }
#pragma unroll
    for (int i = 0; i < 2; i++)
#pragma unroll
        for (int j = 0; j < 2; j++)
            g_Wh[OFF_QKV + (col0 + cg * 2 + j) * 192 + row0 + rg * 2 + i] = __float2half(acc[i][j]);
}

// ---------------- fp16 tensor-core GEMM (fp32 or fp16 output) ----------------
__global__ void __launch_bounds__(256) hgemm_kernel(
    const __half* __restrict__ Ah, int woff, const float* __restrict__ bias,
    const float* __restrict__ addvec, float* __restrict__ C, __half* __restrict__ Ch,
    int Ncol)
{
    __shared__ uint32_t sA[128][36];
    __shared__ uint32_t sB[64][36];
    int t = threadIdx.x;
    int wid = t >> 5, lane = t & 31;
    int wm = wid & 3, wn = wid >> 2;
    int g = lane >> 2, la3 = lane & 3;
    int row0 = blockIdx.y * 128, col0 = blockIdx.x * 64;
    const uint32_t* Whu = (const uint32_t*)(g_Wh + woff);
    const uint32_t* Au = (const uint32_t*)Ah;
    uint32_t sAb = (uint32_t)__cvta_generic_to_shared(&sA[0][0]);
    uint32_t sBb = (uint32_t)__cvta_generic_to_shared(&sB[0][0]);
    float acc[2][4][4] = {};
    for (int kp = 0; kp < 3; kp++) {
        int k0 = kp * 64;
        for (int u = t; u < 4096; u += 256) {
            int r = u >> 5, cu = u & 31;
            uint32_t v = Au[(long)(row0 + r) * 96 + (k0 >> 1) + cu];
            if (addvec) {
                float2 f = __half22float2(*(__half2*)&v);
                f.x += addvec[k0 + 2 * cu];
                f.y += addvec[k0 + 2 * cu + 1];
                v = pack_h2(f.x, f.y);
            }
            sA[r][cu] = v;
        }
        for (int u = t; u < 2048; u += 256) {
            int r = u >> 5, cu = u & 31;
            sB[r][cu] = Whu[(col0 + r) * 96 + (k0 >> 1) + cu];
        }
        __syncthreads();
#pragma unroll
        for (int ks = 0; ks < 4; ks++) {
            uint32_t afr[2][4], bfr[2][4];
#pragma unroll
            for (int mt = 0; mt < 2; mt++) {
                uint32_t addr = sAb + 4 * ((32 * wm + 16 * mt + (lane & 15)) * 36
                                           + ks * 8 + (lane >> 4) * 4);
                ldm_x4(afr[mt], addr);
            }
#pragma unroll
            for (int p = 0; p < 2; p++) {
                uint32_t addr = sBb + 4 * ((32 * wn + 16 * p + (lane >> 4) * 8 + (lane & 7)) * 36
                                           + ks * 8 + ((lane >> 3) & 1) * 4);
                ldm_x4(bfr[p], addr);
            }
#pragma unroll
            for (int nt = 0; nt < 4; nt++) {
                int p = nt >> 1, i0 = (nt & 1) * 2;
                mma_f16(acc[0][nt], afr[0], bfr[p][i0], bfr[p][i0 + 1]);
                mma_f16(acc[1][nt], afr[1], bfr[p][i0], bfr[p][i0 + 1]);
            }
        }
        __syncthreads();
    }
#pragma unroll
    for (int mt = 0; mt < 2; mt++) {
#pragma unroll
        for (int nt = 0; nt < 4; nt++) {
            int col = col0 + 32 * wn + 8 * nt + 2 * la3;
            float b0v = bias ? bias[col] : 0.f;
            float b1v = bias ? bias[col + 1] : 0.f;
            int r = row0 + 32 * wm + 16 * mt + g;
            float o00 = acc[mt][nt][0] + b0v, o01 = acc[mt][nt][1] + b1v;
            float o10 = acc[mt][nt][2] + b0v, o11 = acc[mt][nt][3] + b1v;
            if (Ch) {
                *(uint32_t*)&Ch[(long)r * Ncol + col] = pack_h2(o00, o01);
                *(uint32_t*)&Ch[(long)(r + 8) * Ncol + col] = pack_h2(o10, o11);
            } else {
                *(float2*)&C[(long)r * Ncol + col] = make_float2(o00, o01);
                *(float2*)&C[(long)(r + 8) * Ncol + col] = make_float2(o10, o11);
            }
        }
    }
}

// ---------------- A = knnxyz @ pos_W1 + pos_b1 via tf32 mma (K=48), fp16 out ----------------
__global__ void __launch_bounds__(256) agemm_kernel(const float* __restrict__ pos_b1) {
    __shared__ uint32_t sA[128 * 50];
    __shared__ uint32_t sB[48 * 72];
    int t = threadIdx.x;
    int wid = t >> 5, lane = t & 31;
    int wm = wid & 3, wn = wid >> 2;
    int g = lane >> 2, la3 = lane & 3;
    int row0 = blockIdx.y * 128, col0 = blockIdx.x * 64;
    int m_blk = col0 / 192, cbase = col0 - m_blk * 192;

    for (int u = t; u < 128 * 48; u += 256) {
        int r = u / 48, k = u % 48;
        sA[r * 50 + k] = f2tf32(g_knnxyz[(long)(row0 + r) * 48 + k]);
    }
    for (int u = t; u < 48 * 64; u += 256) {
        int k = u >> 6, n = u & 63;
        sB[k * 72 + n] = g_W1t[k * 576 + col0 + n];
    }
    __syncthreads();

    float acc[2][4][4] = {};
#pragma unroll
    for (int ks = 0; ks < 6; ks++) {
        int ca = ks * 8 + la3;
        uint32_t afr[2][4];
#pragma unroll
        for (int mt = 0; mt < 2; mt++) {
            int r = 32 * wm + 16 * mt + g;
            afr[mt][0] = sA[r * 50 + ca];
            afr[mt][1] = sA[(r + 8) * 50 + ca];
            afr[mt][2] = sA[r * 50 + ca + 4];
            afr[mt][3] = sA[(r + 8) * 50 + ca + 4];
        }
#pragma unroll
        for (int nt = 0; nt < 4; nt++) {
            int nc = 32 * wn + 8 * nt + g;
            uint32_t b0 = sB[ca * 72 + nc];
            uint32_t b1 = sB[(ca + 4) * 72 + nc];
            mma_tf32(acc[0][nt], afr[0], b0, b1);
            mma_tf32(acc[1][nt], afr[1], b0, b1);
        }
    }
#pragma unroll
    for (int mt = 0; mt < 2; mt++) {
#pragma unroll
        for (int nt = 0; nt < 4; nt++) {
            int colL = 32 * wn + 8 * nt + 2 * la3;
            float b0v = pos_b1[col0 + colL], b1v = pos_b1[col0 + colL + 1];
            int r = row0 + 32 * wm + 16 * mt + g;
            *(uint32_t*)&g_Ah[((long)m_blk * NPTS + r) * DIM + cbase + colL] =
                pack_h2(acc[mt][nt][0] + b0v, acc[mt][nt][1] + b1v);
            *(uint32_t*)&g_Ah[((long)m_blk * NPTS + r + 8) * DIM + cbase + colL] =
                pack_h2(acc[mt][nt][2] + b0v, acc[mt][nt][3] + b1v);
        }
    }
}

// ---------------- per-node stage 1 ----------------
__global__ void __launch_bounds__(192) node1_kernel(
    const float* __restrict__ p, const float* __restrict__ x, const int* __restrict__ knn,
    const float* __restrict__ prop_W, const float* __restrict__ prop_b,
    const float* __restrict__ gA_W, const float* __restrict__ gA_b,
    const float* __restrict__ gB_W, const float* __restrict__ gB_b,
    const float* __restrict__ kn, const float* __restrict__ de_W1,
    const float* __restrict__ de_b1, const float* __restrict__ de_W2,
    const float* __restrict__ de_b2)
{
    int n = blockIdx.x;
    int c = threadIdx.x;
    __shared__ float s_p[3];
    __shared__ int   s_idx[NS];
    __shared__ float s_xyz[NS * 3];
    __shared__ float s_pr[NS * 3];
    __shared__ float s_dist[NS];
    __shared__ float s_rep[9];
    __shared__ float s_maxd;
    __shared__ float s_kd[KSP];
    __shared__ float s_g[KSP * DQ];
    __shared__ float s_sc[KSP];
    __shared__ float s_w[DQ];

    if (c < 3) s_p[c] = p[n * 3 + c];
    if (c < NS) s_idx[c] = knn[n * NS + c];
    __syncthreads();

    if (c < NS) {
        int id = s_idx[c];
        float ax = p[id * 3 + 0], ay = p[id * 3 + 1], az = p[id * 3 + 2];
        s_xyz[c * 3 + 0] = ax; s_xyz[c * 3 + 1] = ay; s_xyz[c * 3 + 2] = az;
        float rx = ax - s_p[0], ry = ay - s_p[1], rz = az - s_p[2];
        s_pr[c * 3 + 0] = rx; s_pr[c * 3 + 1] = ry; s_pr[c * 3 + 2] = rz;
        s_dist[c] = sqrtf(rx * rx + ry * ry + rz * rz + 1e-12f);
    }
    if (c >= 32 && c < 32 + KSP) {
        int s = c - 32;
        float dx = s_p[0] - kn[s * 3 + 0];
        float dy = s_p[1] - kn[s * 3 + 1];
        float dz = s_p[2] - kn[s * 3 + 2];
        s_kd[s] = sqrtf(dx * dx + dy * dy + dz * dz + 1e-12f);
    }
    __syncthreads();

    if (c == 0) {
        float mx = 0, my = 0, mz = 0, qx = 0, qy = 0, qz = 0, md = 0, sd = 0;
        for (int j = 0; j < NS; j++) {
            mx += s_pr[j * 3]; my += s_pr[j * 3 + 1]; mz += s_pr[j * 3 + 2];
            qx += s_xyz[j * 3]; qy += s_xyz[j * 3 + 1]; qz += s_xyz[j * 3 + 2];
            md = fmaxf(md, s_dist[j]); sd += s_dist[j];
        }
        const float inv = 1.f / NS;
        s_rep[0] = mx * inv; s_rep[1] = my * inv; s_rep[2] = mz * inv;
        s_rep[3] = qx * inv; s_rep[4] = qy * inv; s_rep[5] = qz * inv;
        s_rep[6] = s_p[0]; s_rep[7] = s_p[1]; s_rep[8] = s_p[2];
        s_maxd = md;
        g_distsum[n] = sd; g_distmax[n] = md;
        g_m3[n * 3 + 0] = qx; g_m3[n * 3 + 1] = qy; g_m3[n * 3 + 2] = qz;
    }
    if (c < NS * 3) g_knnxyz[n * 48 + c] = s_xyz[c];
    for (int idx = c; idx < KSP * DQ; idx += 192) {
        int s = idx / DQ, k = idx % DQ;
        s_g[idx] = fmaxf(s_kd[s] * de_W1[k] + de_b1[k], 0.f);
    }
    __syncthreads();

    if (c < KSP) {
        float l = g_kpconst;
        for (int k = 0; k < DQ; k++) l += s_g[c * DQ + k] * g_kpwproj[k];
        s_sc[c] = l;
    }
    __syncthreads();
    if (c == 0) {
        float mx = -1e30f;
        for (int s = 0; s < KSP; s++) mx = fmaxf(mx, s_sc[s]);
        float se = 0.f;
        for (int s = 0; s < KSP; s++) { float e = expf(s_sc[s] - mx); s_sc[s] = e; se += e; }
        float inv = 1.f / se;
        for (int s = 0; s < KSP; s++) s_sc[s] *= inv;
    }
    __syncthreads();
    if (c < DQ) {
        float w = 0.f;
        for (int s = 0; s < KSP; s++) w += s_sc[s] * s_g[s * DQ + c];
        s_w[c] = w;
    }
    __syncthreads();

    float dist_feat = de_b2[c];
#pragma unroll
    for (int k = 0; k < DQ; k++) dist_feat += s_w[k] * de_W2[k * DIM + c];

    float geo = gA_b[c] + gB_b[c] + s_maxd * gB_W[c];
#pragma unroll
    for (int i = 0; i < 9; i++) geo += s_rep[i] * gA_W[i * DIM + c];

    float w0 = prop_W[192 * DIM + c], w1 = prop_W[193 * DIM + c], w2 = prop_W[194 * DIM + c];
    float pb = prop_b[c];
    float msg = 0.f;
#pragma unroll
    for (int s = 0; s < NS; s++) {
        float v = __half2float(g_xpwh[(long)s_idx[s] * DIM + c])
                + s_pr[s * 3] * w0 + s_pr[s * 3 + 1] * w1 + s_pr[s * 3 + 2] * w2 + pb;
        msg += fmaxf(v, 0.f);
    }
    msg *= (1.f / NS);
    g_prefh[(long)n * DIM + c] = __float2half(x[(long)n * DIM + c] + msg + geo + dist_feat);
}

// ---------------- global reductions ----------------
__global__ void __launch_bounds__(256) reduce_kernel() {
    int tid = blockIdx.x * blockDim.x + threadIdx.x;
    int stride = gridDim.x * blockDim.x;
    double lsum = 0, l0 = 0, l1 = 0, l2 = 0;
    float lmax = 0.f;
    for (int n = tid; n < NPTS; n += stride) {
        lsum += (double)g_distsum[n];
        lmax = fmaxf(lmax, g_distmax[n]);
        l0 += (double)g_m3[n * 3 + 0];
        l1 += (double)g_m3[n * 3 + 1];
        l2 += (double)g_m3[n * 3 + 2];
    }
    double m0 = 0, m1 = 0, m2 = 0, m3v = 0, m4 = 0, m5 = 0;
    for (int idx = tid; idx < NPTS * NS; idx += stride) {
        float xx = g_knnxyz[idx * 3 + 0];
        float yy = g_knnxyz[idx * 3 + 1];
        float zz = g_knnxyz[idx * 3 + 2];
        m0 += (double)xx * xx; m1 += (double)xx * yy; m2 += (double)xx * zz;
        m3v += (double)yy * yy; m4 += (double)yy * zz; m5 += (double)zz * zz;
    }
    lsum = dwarpsum(lsum); l0 = dwarpsum(l0); l1 = dwarpsum(l1); l2 = dwarpsum(l2);
    m0 = dwarpsum(m0); m1 = dwarpsum(m1); m2 = dwarpsum(m2);
    m3v = dwarpsum(m3v); m4 = dwarpsum(m4); m5 = dwarpsum(m5);
#pragma unroll
    for (int o = 16; o > 0; o >>= 1) lmax = fmaxf(lmax, __shfl_xor_sync(0xffffffffu, lmax, o));
    if ((threadIdx.x & 31) == 0) {
        atomicAdd(&g_sumdist, lsum);
        atomicAdd(&g_Sm3[0], l0); atomicAdd(&g_Sm3[1], l1); atomicAdd(&g_Sm3[2], l2);
        atomicAdd(&g_SM33[0], m0); atomicAdd(&g_SM33[1], m1); atomicAdd(&g_SM33[2], m2);
        atomicAdd(&g_SM33[3], m3v); atomicAdd(&g_SM33[4], m4); atomicAdd(&g_SM33[5], m5);
        atomicMax(&g_maxbits, __float_as_int(lmax));
    }
}

// ---------------- BN per-channel statistics (reads fp16 A) ----------------
#define BNCHUNK 64
__global__ void __launch_bounds__(192) bnstats_kernel() {
    int m = blockIdx.y;
    int n0 = blockIdx.x * BNCHUNK;
    int c = threadIdx.x;
    float sa = 0, sa2 = 0, sx = 0, sy = 0, sz = 0;
    const __half* Abase = g_Ah + (long)m * NPTS * DIM;
    for (int n = n0; n < n0 + BNCHUNK; n++) {
        float a = __half2float(Abase[(long)n * DIM + c]);
        float mx = g_m3[n * 3 + 0], my = g_m3[n * 3 + 1], mz = g_m3[n * 3 + 2];
        sa += a;
        sa2 += a * a;
        sx += a * mx; sy += a * my; sz += a * mz;
    }
    double* d = g_ch + ((long)m * DIM + c) * 5;
    atomicAdd(d + 0, (double)sa); atomicAdd(d + 1, (double)sa2);
    atomicAdd(d + 2, (double)sx); atomicAdd(d + 3, (double)sy); atomicAdd(d + 4, (double)sz);
}

// ---------------- finalize ----------------
__global__ void __launch_bounds__(192) finalize_kernel(
    const float* __restrict__ pos_W1, const float* __restrict__ pos_gamma,
    const float* __restrict__ pos_beta, const float* __restrict__ gC_W,
    const float* __restrict__ gC_b)
{
    int c = threadIdx.x;
    float Sv[3][3];
#pragma unroll
    for (int m = 0; m < 3; m++)
#pragma unroll
        for (int k = 0; k < 3; k++) {
            float s = 0.f;
            for (int j = 0; j < NS; j++) s += pos_W1[(long)m * 48 * DIM + (3 * j + k) * DIM + c];
            Sv[m][k] = s;
            g_S[(m * 3 + k) * DIM + c] = s;
        }
    const double T = (double)NPTS * NS;
    double Q0 = g_SM33[0], Q1 = g_SM33[1], Q2 = g_SM33[2], Q3 = g_SM33[3], Q4 = g_SM33[4], Q5 = g_SM33[5];
    double P0 = g_Sm3[0], P1 = g_Sm3[1], P2 = g_Sm3[2];
#pragma unroll
    for (int m = 0; m < 3; m++) {
        const double* d = g_ch + ((long)m * DIM + c) * 5;
        double SA = d[0], SA2 = d[1], SMx = d[2], SMy = d[3], SMz = d[4];
        double Sx = Sv[m][0], Sy = Sv[m][1], Sz = Sv[m][2];
        double mean = (16.0 * SA - (Sx * P0 + Sy * P1 + Sz * P2)) / T;
        double sq = 16.0 * SA2 - 2.0 * (Sx * SMx + Sy * SMy + Sz * SMz)
                  + Sx * Sx * Q0 + Sy * Sy * Q3 + Sz * Sz * Q5
                  + 2.0 * (Sx * Sy * Q1 + Sx * Sz * Q2 + Sy * Sz * Q4);
        double var = sq / T - mean * mean;
        float sc = pos_gamma[m * DIM + c] * rsqrtf((float)(var + 1e-5));
        g_bnscale[m * DIM + c] = sc;
        g_bnshift[m * DIM + c] = pos_beta[m * DIM + c] - (float)mean * sc;
    }
    float maxd = __int_as_float(g_maxbits);
    float vol = (float)(g_sumdist / T) / (maxd + 1e-8f);
    g_volvec[c] = vol * gC_W[c] + gC_b[c];
}

// ---------------- fused attention: U-factorized scores + proven pv path ----------------
#define SH_OFF    0          // 2 x 128 x 100 u32 = 102400
#define SU_OFF    102400     // 36864
#define SQ_OFF    139264     // 6144
#define SK_OFF    145408     // 6144
#define SQH_OFF   151552     // 6400
#define SKH_OFF   157952     // 6400
#define SB2_OFF   164352     // 2304
#define SSC_OFF   166656     // 3072
#define SWT_OFF   169728     // 3072
#define SXYZ_OFF  172800     // 1536
#define SIDX_OFF  174336     // 512
#define SAH_OFF   174848     // 18432
#define SSH_OFF   193280     // 6912
#define ATT_SMEM  200192

__global__ void __launch_bounds__(512, 1) attn_mma_kernel(
    const int* __restrict__ knn, const float* __restrict__ pos_b2)
{
    extern __shared__ char smem[];
    const int t = threadIdx.x;
    const int wid = t >> 5, lane = t & 31;
    const int wm = wid & 3, wn = wid >> 2;
    const int g = lane >> 2, la3 = lane & 3;
    const int nb = blockIdx.x * 8;

    uint32_t* s_h  = (uint32_t*)(smem + SH_OFF);
    uint32_t* s_u  = (uint32_t*)(smem + SU_OFF);
    float* s_q   = (float*)(smem + SQ_OFF);
    float* s_k0  = (float*)(smem + SK_OFF);
    uint32_t* s_qh = (uint32_t*)(smem + SQH_OFF);
    uint32_t* s_kh = (uint32_t*)(smem + SKH_OFF);
    float* s_b2  = (float*)(smem + SB2_OFF);
    float* s_sc  = (float*)(smem + SSC_OFF);
    float* s_w   = (float*)(smem + SWT_OFF);
    float* s_xyz = (float*)(smem + SXYZ_OFF);
    int*   s_idx = (int*)(smem + SIDX_OFF);
    float* s_ahat = (float*)(smem + SAH_OFF);
    float* s_Sh   = (float*)(smem + SSH_OFF);
    const uint32_t shb  = (uint32_t)__cvta_generic_to_shared(smem + SH_OFF);
    const uint32_t sqhb = (uint32_t)__cvta_generic_to_shared(smem + SQH_OFF);
    const uint32_t skhb = (uint32_t)__cvta_generic_to_shared(smem + SKH_OFF);

    const int grow = t >> 2;
    const int gn2 = grow >> 4, gj2 = grow & 15;

    // ---- phase A: stage shared inputs ----
    for (int u = t; u < 128; u += 512) s_idx[u] = knn[(nb + (u >> 4)) * NS + (u & 15)];
    for (int u = t; u < 8 * 48; u += 512) s_xyz[u] = g_knnxyz[(long)nb * 48 + u];
    for (int u = t; u < 3 * DIM; u += 512) s_b2[u] = pos_b2[u];
    for (int u = t; u < 8 * (DIM / 2); u += 512) {
        int n = u / (DIM / 2), cp = u % (DIM / 2);
        long r0h = (long)knn[(nb + n) * NS] * 288;   // row base in uint32 units
        float2 qv = up_h2(((const uint32_t*)g_qkvh)[r0h + cp]);
        float2 kv = up_h2(((const uint32_t*)g_qkvh)[r0h + 96 + cp]);
        *(float2*)&s_q[n * DIM + 2 * cp] = qv;
        *(float2*)&s_k0[n * DIM + 2 * cp] = kv;
    }
    for (int u = t; u < 3 * 8 * (DIM / 2); u += 512) {
        int m = u / (8 * (DIM / 2));
        int rem = u - m * 8 * (DIM / 2);
        int node = rem / (DIM / 2), cp = rem % (DIM / 2);
        int cg = 2 * cp;
        float2 a2 = up_h2(((const uint32_t*)g_Ah)[((long)m * NPTS + nb + node) * (DIM / 2) + cp]);
        s_ahat[m * 8 * DIM + node * DIM + cg] =
            a2.x * g_bnscale[m * DIM + cg] + g_bnshift[m * DIM + cg];
        s_ahat[m * 8 * DIM + node * DIM + cg + 1] =
            a2.y * g_bnscale[m * DIM + cg + 1] + g_bnshift[m * DIM + cg + 1];
    }
    for (int u = t; u < 3 * 3 * DIM; u += 512) {
        int m = u / (3 * DIM);
        int rem = u - m * 3 * DIM;
        s_Sh[u] = g_S[(m * 3 + rem / DIM) * DIM + (rem % DIM)] * g_bnscale[m * DIM + rem % DIM];
    }
    __syncthreads();

    // ---- phase B: base scores + gen h (mats 0,1) + fp16 q0/k0 staging ----
    for (int task = t; task < 768; task += 512) {
        int n = task / 96, h = (task / 16) % 6, j = task & 15;
        const float4* qv = (const float4*)(s_q + n * DIM + 32 * h);
        const float4* kv0 = (const float4*)(s_k0 + n * DIM + 32 * h);
        const float4* b0 = (const float4*)(s_b2 + 32 * h);
        const float4* b1 = (const float4*)(s_b2 + DIM + 32 * h);
        const uint4* kj = (const uint4*)((const uint32_t*)g_qkvh
                            + (long)s_idx[n * 16 + j] * 288 + 96 + 16 * h);
        float dot = 0.f;
#pragma unroll
        for (int u = 0; u < 4; u++) {
            uint4 kk = kj[u];
            float2 k0p = up_h2(kk.x), k1p = up_h2(kk.y), k2p = up_h2(kk.z), k3p = up_h2(kk.w);
            float4 q4a = qv[2 * u], q4b = qv[2 * u + 1];
            float4 b0a = b0[2 * u], b0b = b0[2 * u + 1];
            float4 b1a = b1[2 * u], b1b = b1[2 * u + 1];
            float4 kka = kv0[2 * u], kkb = kv0[2 * u + 1];
            dot += q4a.x * (k0p.x + b0a.x) + q4a.y * (k0p.y + b0a.y)
                 + q4a.z * (k1p.x + b0a.z) + q4a.w * (k1p.y + b0a.w)
                 + q4b.x * (k2p.x + b0b.x) + q4b.y * (k2p.y + b0b.y)
                 + q4b.z * (k3p.x + b0b.z) + q4b.w * (k3p.y + b0b.w);
            dot += kka.x * b1a.x + kka.y * b1a.y + kka.z * b1a.z + kka.w * b1a.w
                 + kkb.x * b1b.x + kkb.y * b1b.y + kkb.z * b1b.z + kkb.w * b1b.w;
        }
        s_sc[(n * 6 + h) * 16 + j] = dot;
    }
    {
        float xx = s_xyz[gn2 * 48 + gj2 * 3 + 0];
        float yy = s_xyz[gn2 * 48 + gj2 * 3 + 1];
        float zz = s_xyz[gn2 * 48 + gj2 * 3 + 2];
#pragma unroll
        for (int m = 0; m < 2; m++) {
            const float* ah = s_ahat + m * 8 * DIM + gn2 * DIM;
            const float* Sh = s_Sh + m * 3 * DIM;
            uint32_t* hdst = s_h + m * 12800 + grow * 100;
#pragma unroll
            for (int i = 0; i < 24; i++) {
                int cu = (t & 3) + 4 * i;
                int cg = 2 * cu;
                float2 a2 = *(const float2*)&ah[cg];
                float2 S0 = *(const float2*)&Sh[cg];
                float2 S1 = *(const float2*)&Sh[DIM + cg];
                float2 S2 = *(const float2*)&Sh[2 * DIM + cg];
                float h0 = a2.x - (xx * S0.x + yy * S1.x + zz * S2.x);
                float h1 = a2.y - (xx * S0.y + yy * S1.y + zz * S2.y);
                hdst[cu] = pack_h2(fmaxf(h0, 0.f), fmaxf(h1, 0.f));
            }
        }
    }
    for (int u = t; u < 1600; u += 512) {
        int row = u / 100, cu = u % 100;
        uint32_t vq = 0, vk = 0;
        if (row < 8 && cu < 96) {
            vq = pack_h2(s_q[row * DIM + 2 * cu], s_q[row * DIM + 2 * cu + 1]);
            vk = pack_h2(s_k0[row * DIM + 2 * cu], s_k0[row * DIM + 2 * cu + 1]);
        }
        s_qh[u] = vq;
        s_kh[u] = vk;
    }
    __syncthreads();

    // ---- phase C: U-mma (12 warps) ----
    if (wid < 12) {
        int m = wid / 6, hh = wid % 6;
        uint32_t xb = (m == 0) ? sqhb : skhb;
        const uint2* wt = g_W2u + ((m * 6 + hh) * 24) * 64;
#pragma unroll 4
        for (int nt = 0; nt < 24; nt++) {
            float acc[4] = {0.f, 0.f, 0.f, 0.f};
#pragma unroll
            for (int ks = 0; ks < 2; ks++) {
                uint32_t afr[4];
                ldm_x4(afr, xb + 4 * ((lane & 15) * 100 + 16 * hh + ks * 8 + (lane >> 4) * 4));
                uint2 bb = wt[(nt * 2 + ks) * 32 + lane];
                mma_f16(acc, afr, bb.x, bb.y);
            }
            s_u[((m * 8 + g) * 6 + hh) * 96 + 4 * nt + la3] = pack_h2(acc[0], acc[1]);
        }
    }
    __syncthreads();

    // ---- phase C2: score-mma (16 warps) ----
    {
        int m = wid >> 3, n = wid & 7;
        float acc[4] = {0.f, 0.f, 0.f, 0.f};
        const uint32_t* ub = s_u + (m * 8 + n) * 6 * 96;
#pragma unroll
        for (int ks = 0; ks < 12; ks++) {
            uint32_t afr[4];
            ldm_x4(afr, shb + 4 * (m * 12800 + (n * 16 + (lane & 15)) * 100 + ks * 8 + (lane >> 4) * 4));
            uint32_t b0 = 0, b1 = 0;
            if (g < 6) {
                b0 = ub[g * 96 + ks * 8 + la3];
                b1 = ub[g * 96 + ks * 8 + la3 + 4];
            }
            mma_f16(acc, afr, b0, b1);
        }
        int h0 = 2 * la3;
        if (h0 < 6) {
            atomicAdd(&s_sc[(n * 6 + h0) * 16 + g], acc[0]);
            atomicAdd(&s_sc[(n * 6 + h0) * 16 + g + 8], acc[2]);
        }
        if (h0 + 1 < 6) {
            atomicAdd(&s_sc[(n * 6 + h0 + 1) * 16 + g], acc[1]);
            atomicAdd(&s_sc[(n * 6 + h0 + 1) * 16 + g + 8], acc[3]);
        }
    }
    __syncthreads();

    // ---- phase D: softmax + gen h mat 2 (into buffer 0) ----
    {
        float xx = s_xyz[gn2 * 48 + gj2 * 3 + 0];
        float yy = s_xyz[gn2 * 48 + gj2 * 3 + 1];
        float zz = s_xyz[gn2 * 48 + gj2 * 3 + 2];
        const float* ah = s_ahat + 2 * 8 * DIM + gn2 * DIM;
        const float* Sh = s_Sh + 2 * 3 * DIM;
        uint32_t* hdst = s_h + grow * 100;
#pragma unroll
        for (int i = 0; i < 24; i++) {
            int cu = (t & 3) + 4 * i;
            int cg = 2 * cu;
            float2 a2 = *(const float2*)&ah[cg];
            float2 S0 = *(const float2*)&Sh[cg];
            float2 S1 = *(const float2*)&Sh[DIM + cg];
            float2 S2 = *(const float2*)&Sh[2 * DIM + cg];
            float h0 = a2.x - (xx * S0.x + yy * S1.x + zz * S2.x);
            float h1 = a2.y - (xx * S0.y + yy * S1.y + zz * S2.y);
            hdst[cu] = pack_h2(fmaxf(h0, 0.f), fmaxf(h1, 0.f));
        }
    }
    if (t < 48) {
        const float scale = 0.17677669529663687f;  // 32^-0.5
        float* sc = s_sc + t * 16;
        float mx = -1e30f;
#pragma unroll
        for (int j = 0; j < 16; j++) mx = fmaxf(mx, sc[j]);
        float se = 0.f;
        float ev[16];
#pragma unroll
        for (int j = 0; j < 16; j++) { ev[j] = expf((sc[j] - mx) * scale); se += ev[j]; }
        float inv = 1.f / se;
#pragma unroll
        for (int j = 0; j < 16; j++) s_w[t * 16 + j] = ev[j] * inv;
    }
    __syncthreads();

    // ---- phase E: pv-mma (16 warps) + output epilogue ----
    {
        float acc[2][6][4];
#pragma unroll
        for (int a1 = 0; a1 < 2; a1++)
#pragma unroll
            for (int a2 = 0; a2 < 6; a2++)
#pragma unroll
                for (int a3 = 0; a3 < 4; a3++) acc[a1][a2][a3] = 0.f;

#pragma unroll
        for (int ks = 0; ks < 12; ks++) {
            const uint4* bq = (const uint4*)g_W2f + (((2 * 4 + wn) * 12 + ks) * 3) * 32;
            uint4 u0 = bq[lane];
            uint4 u1 = bq[32 + lane];
            uint4 u2 = bq[64 + lane];
            uint32_t afr[2][4];
#pragma unroll
            for (int mt = 0; mt < 2; mt++) {
                uint32_t addr = shb + 4 * ((32 * wm + 16 * mt + (lane & 15)) * 100
                                           + ks * 8 + (lane >> 4) * 4);
                ldm_x4(afr[mt], addr);
            }
            mma_f16(acc[0][0], afr[0], u0.x, u0.y);
            mma_f16(acc[1][0], afr[1], u0.x, u0.y);
            mma_f16(acc[0][1], afr[0], u0.z, u0.w);
            mma_f16(acc[1][1], afr[1], u0.z, u0.w);
            mma_f16(acc[0][2], afr[0], u1.x, u1.y);
            mma_f16(acc[1][2], afr[1], u1.x, u1.y);
            mma_f16(acc[0][3], afr[0], u1.z, u1.w);
            mma_f16(acc[1][3], afr[1], u1.z, u1.w);
            mma_f16(acc[0][4], afr[0], u2.x, u2.y);
            mma_f16(acc[1][4], afr[1], u2.x, u2.y);
            mma_f16(acc[0][5], afr[0], u2.z, u2.w);
            mma_f16(acc[1][5], afr[1], u2.z, u2.w);
        }

#pragma unroll
        for (int mt = 0; mt < 2; mt++) {
            int node = 2 * wm + mt;
            int j0 = g;
            long v0b = (long)s_idx[node * 16 + j0] * 288 + 192;   // uint32 units
            long v1b = (long)s_idx[node * 16 + j0 + 8] * 288 + 192;
#pragma unroll
            for (int nt = 0; nt < 6; nt++) {
                int c0 = 48 * wn + 8 * nt + 2 * la3;
                int h = c0 >> 5;
                float w0 = s_w[(node * 6 + h) * 16 + j0];
                float w1 = s_w[(node * 6 + h) * 16 + j0 + 8];
                float b20 = s_b2[2 * DIM + c0], b21 = s_b2[2 * DIM + c0 + 1];
                float2 v0p = up_h2(((const uint32_t*)g_qkvh)[v0b + (c0 >> 1)]);
                float2 v1p = up_h2(((const uint32_t*)g_qkvh)[v1b + (c0 >> 1)]);
                float o0 = w0 * (acc[mt][nt][0] + v0p.x + b20)
                         + w1 * (acc[mt][nt][2] + v1p.x + b20);
                float o1 = w0 * (acc[mt][nt][1] + v0p.y + b21)
                         + w1 * (acc[mt][nt][3] + v1p.y + b21);
#pragma unroll
                for (int o = 4; o < 32; o <<= 1) {
                    o0 += __shfl_xor_sync(0xffffffffu, o0, o);
                    o1 += __shfl_xor_sync(0xffffffffu, o1, o);
                }
                if (g == 0) {
                    *(uint32_t*)(g_atth + (long)(nb + node) * DIM + c0) = pack_h2(o0, o1);
                }
            }
        }
    }
}

// ---------------- host launcher ----------------
extern "C" void kernel_launch(void* const* d_in, const int* in_sizes, int n_in,
                              void* d_out, int out_size)
{
    const float* p      = (const float*)d_in[0];
    const float* x      = (const float*)d_in[1];
    const int*   knn    = (const int*)d_in[2];
    const float* W_qkv  = (const float*)d_in[3];
    const float* W_proj = (const float*)d_in[4];
    const float* b_proj = (const float*)d_in[5];
    const float* prop_W = (const float*)d_in[6];
    const float* prop_b = (const float*)d_in[7];
    const float* gA_W   = (const float*)d_in[8];
    const float* gA_b   = (const float*)d_in[9];
    const float* gB_W   = (const float*)d_in[10];
    const float* gB_b   = (const float*)d_in[11];
    const float* gC_W   = (const float*)d_in[12];
    const float* gC_b   = (const float*)d_in[13];
    const float* pos_W1 = (const float*)d_in[14];
    const float* pos_b1 = (const float*)d_in[15];
    const float* pos_gamma = (const float*)d_in[16];
    const float* pos_beta  = (const float*)d_in[17];
    const float* pos_W2 = (const float*)d_in[18];
    const float* pos_b2 = (const float*)d_in[19];
    const float* kn     = (const float*)d_in[20];
    const float* de_W1  = (const float*)d_in[21];
    const float* de_b1  = (const float*)d_in[22];
    const float* de_W2  = (const float*)d_in[23];
    const float* de_b2  = (const float*)d_in[24];
    const float* kp_W   = (const float*)d_in[25];
    const float* kp_b   = (const float*)d_in[26];
    const float* fus_W  = (const float*)d_in[27];
    const float* fus_b  = (const float*)d_in[28];
    float* out = (float*)d_out;

    float *volvec, *bfq;
    __half *xh, *prefh, *atth, *qkvh, *xpwh;
    cudaGetSymbolAddress((void**)&volvec, g_volvec);
    cudaGetSymbolAddress((void**)&bfq, g_bfq);
    cudaGetSymbolAddress((void**)&xh, g_xh);
    cudaGetSymbolAddress((void**)&prefh, g_prefh);
    cudaGetSymbolAddress((void**)&atth, g_atth);
    cudaGetSymbolAddress((void**)&qkvh, g_qkvh);
    cudaGetSymbolAddress((void**)&xpwh, g_xpwh);

    cudaFuncSetAttribute(attn_mma_kernel, cudaFuncAttributeMaxDynamicSharedMemorySize, ATT_SMEM);

    prep_kernel<<<512, 256>>>(prop_W, W_proj, pos_W1, x);
    small_kernel<<<4, 192>>>(de_W2, de_b2, kp_W, kp_b, fus_b, W_qkv);
    w2f_kernel<<<216, 256>>>(pos_W2);
    w2u_kernel<<<144, 256>>>(pos_W2);
    wfq_kernel<<<dim3(18, 6), 256>>>(fus_W, W_qkv);
    hgemm_kernel<<<dim3(3, 128), 256>>>(xh, OFF_PROP, nullptr, nullptr, nullptr, xpwh, 192);
    node1_kernel<<<NPTS, 192>>>(p, x, knn, prop_W, prop_b, gA_W, gA_b, gB_W, gB_b,
                                kn, de_W1, de_b1, de_W2, de_b2);
    agemm_kernel<<<dim3(9, 128), 256>>>(pos_b1);
    reduce_kernel<<<128, 256>>>();
    bnstats_kernel<<<dim3(NPTS / BNCHUNK, 3), 192>>>();
    finalize_kernel<<<1, 192>>>(pos_W1, pos_gamma, pos_beta, gC_W, gC_b);
    hgemm_kernel<<<dim3(9, 128), 256>>>(prefh, OFF_QKV, bfq, volvec, nullptr, qkvh, 576);
    attn_mma_kernel<<<NPTS / 8, 512, ATT_SMEM>>>(knn, pos_b2);
    hgemm_kernel<<<dim3(3, 128), 256>>>(atth, OFF_PROJ, b_proj, nullptr, out, nullptr, 192);
}